// round 1
// baseline (speedup 1.0000x reference)
#include <cuda_runtime.h>
#include <cuda_bf16.h>
#include <cstdint>

// ============================================================================
// FactoredCausalSelfAttention  (B=2, T=2048, C=1024, H=16, D=64)
//   qk = x_norm @ W_attn + b        -> q,k split, head-transposed
//   y  = causal_softmax(q k^T / 8) @ v   with v = reshape(xt_current)
// Round 0: fp32 everywhere (correctness + baseline profile).
// ============================================================================

#define B_   2
#define T_   2048
#define C_   1024
#define H_   16
#define D_   64
#define M_GEMM (B_*T_)      // 4096
#define N_GEMM (2*C_)       // 2048
#define K_GEMM (C_)         // 1024

// scratch: head-transposed q and k, [B*H][T][D] fp32
__device__ float g_q[(size_t)B_*H_*T_*D_];
__device__ float g_k[(size_t)B_*H_*T_*D_];

// ----------------------------------------------------------------------------
// GEMM: qk = X[4096,1024] @ W[1024,2048] + bias, scatter to g_q / g_k
// 128x128 block tile, BK=8, 8x8 microtile, 256 threads
// ----------------------------------------------------------------------------
__global__ __launch_bounds__(256) void gemm_qk_kernel(
    const float* __restrict__ X,
    const float* __restrict__ W,
    const float* __restrict__ bias)
{
    __shared__ float As[8][128];   // [k][m]  (A stored transposed)
    __shared__ float Bs[8][128];   // [k][n]

    const int bx = blockIdx.x;     // n-tile (0..15)
    const int by = blockIdx.y;     // m-tile (0..31)
    const int tid = threadIdx.x;
    const int tx = tid & 15;       // 0..15 -> n micro
    const int ty = tid >> 4;       // 0..15 -> m micro

    // A tile load: 128 rows x 8 cols = 256 float4, one per thread
    const int a_row  = tid >> 1;          // 0..127
    const int a_col4 = (tid & 1) * 4;     // 0 or 4
    // B tile load: 8 rows x 128 cols = 256 float4
    const int b_row  = tid >> 5;          // 0..7
    const int b_col4 = (tid & 31) * 4;    // 0..124

    const float* Aptr = X + (size_t)(by*128 + a_row) * K_GEMM + a_col4;
    const float* Bptr = W + (size_t)b_row * N_GEMM + bx*128 + b_col4;

    float acc[8][8];
    #pragma unroll
    for (int i = 0; i < 8; i++)
        #pragma unroll
        for (int j = 0; j < 8; j++) acc[i][j] = 0.f;

    for (int k0 = 0; k0 < K_GEMM; k0 += 8) {
        float4 av = *(const float4*)(Aptr + k0);
        float4 bv = *(const float4*)(Bptr + (size_t)k0 * N_GEMM);
        As[a_col4+0][a_row] = av.x;
        As[a_col4+1][a_row] = av.y;
        As[a_col4+2][a_row] = av.z;
        As[a_col4+3][a_row] = av.w;
        *(float4*)&Bs[b_row][b_col4] = bv;
        __syncthreads();

        #pragma unroll
        for (int kk = 0; kk < 8; kk++) {
            float4 ra0 = *(const float4*)&As[kk][ty*8];
            float4 ra1 = *(const float4*)&As[kk][ty*8+4];
            float4 rb0 = *(const float4*)&Bs[kk][tx*8];
            float4 rb1 = *(const float4*)&Bs[kk][tx*8+4];
            float ra[8] = {ra0.x,ra0.y,ra0.z,ra0.w, ra1.x,ra1.y,ra1.z,ra1.w};
            float rb[8] = {rb0.x,rb0.y,rb0.z,rb0.w, rb1.x,rb1.y,rb1.z,rb1.w};
            #pragma unroll
            for (int i = 0; i < 8; i++)
                #pragma unroll
                for (int j = 0; j < 8; j++)
                    acc[i][j] += ra[i] * rb[j];
        }
        __syncthreads();
    }

    // epilogue: bias + scatter into head-transposed q/k
    #pragma unroll
    for (int i = 0; i < 8; i++) {
        const int m = by*128 + ty*8 + i;
        const int b = m >> 11;             // /2048
        const int t = m & (T_-1);
        #pragma unroll
        for (int j = 0; j < 8; j++) {
            const int n = bx*128 + tx*8 + j;
            float v = acc[i][j] + bias[n];
            if (n < C_) {
                const int h = n >> 6, d = n & 63;
                g_q[(((size_t)(b*H_+h))*T_ + t)*D_ + d] = v;
            } else {
                const int n2 = n - C_;
                const int h = n2 >> 6, d = n2 & 63;
                g_k[(((size_t)(b*H_+h))*T_ + t)*D_ + d] = v;
            }
        }
    }
}

// ----------------------------------------------------------------------------
// Flash attention (causal), fp32. One q-row per thread; 128 rows per CTA.
// K/V staged in smem in 64-row tiles; broadcast LDS reads.
// ----------------------------------------------------------------------------
__global__ __launch_bounds__(128) void attn_kernel(
    const float* __restrict__ xt,   // [B,T,C] -> v
    float* __restrict__ out)        // [B,T,C]
{
    __shared__ float Ks[64][64];
    __shared__ float Vs[64][64];

    const int bh = blockIdx.y;
    const int b  = bh >> 4;
    const int h  = bh & 15;
    const int tid = threadIdx.x;
    // schedule heavy (high-row) tiles first for tail balance
    const int qt = gridDim.x - 1 - blockIdx.x;
    const int t  = qt*128 + tid;

    float q[64], o[64];
    {
        const float4* qp = (const float4*)(g_q + ((size_t)bh*T_ + t)*D_);
        #pragma unroll
        for (int i = 0; i < 16; i++) {
            float4 v = qp[i];
            q[4*i+0]=v.x; q[4*i+1]=v.y; q[4*i+2]=v.z; q[4*i+3]=v.w;
        }
    }
    #pragma unroll
    for (int d = 0; d < 64; d++) o[d] = 0.f;

    float mrun = -1e30f, l = 0.f;
    const float scale = 0.125f;
    const int jmax = qt*128 + 127;    // last key any row in this CTA needs

    for (int j0 = 0; j0 <= jmax; j0 += 64) {
        // cooperative load of 64x64 K and V tiles (1024 float4 each)
        #pragma unroll
        for (int it = 0; it < 8; it++) {
            const int idx = tid + it*128;      // 0..1023
            const int r   = idx >> 4;
            const int c4  = (idx & 15) * 4;
            *(float4*)&Ks[r][c4] =
                *(const float4*)(g_k + ((size_t)bh*T_ + j0 + r)*D_ + c4);
            *(float4*)&Vs[r][c4] =
                *(const float4*)(xt + ((size_t)(b*T_ + j0 + r))*C_ + h*D_ + c4);
        }
        __syncthreads();

        #pragma unroll 2
        for (int jj = 0; jj < 64; jj++) {
            // ---- score = q . k_jj  (4 accumulator chains) ----
            const float4* kr = (const float4*)&Ks[jj][0];
            float a0=0.f, a1=0.f, a2=0.f, a3=0.f;
            #pragma unroll
            for (int d4 = 0; d4 < 16; d4 += 4) {
                float4 k0v = kr[d4+0], k1v = kr[d4+1], k2v = kr[d4+2], k3v = kr[d4+3];
                a0 += q[4*(d4+0)+0]*k0v.x + q[4*(d4+0)+1]*k0v.y + q[4*(d4+0)+2]*k0v.z + q[4*(d4+0)+3]*k0v.w;
                a1 += q[4*(d4+1)+0]*k1v.x + q[4*(d4+1)+1]*k1v.y + q[4*(d4+1)+2]*k1v.z + q[4*(d4+1)+3]*k1v.w;
                a2 += q[4*(d4+2)+0]*k2v.x + q[4*(d4+2)+1]*k2v.y + q[4*(d4+2)+2]*k2v.z + q[4*(d4+2)+3]*k2v.w;
                a3 += q[4*(d4+3)+0]*k3v.x + q[4*(d4+3)+1]*k3v.y + q[4*(d4+3)+2]*k3v.z + q[4*(d4+3)+3]*k3v.w;
            }
            float sc = (a0+a1) + (a2+a3);
            sc = (j0 + jj <= t) ? sc * scale : -1e30f;

            // ---- online softmax (rescale only on new max: rare) ----
            if (sc > mrun) {
                const float alpha = __expf(mrun - sc);
                mrun = sc;
                l *= alpha;
                #pragma unroll
                for (int d = 0; d < 64; d++) o[d] *= alpha;
            }
            const float p = __expf(sc - mrun);
            l += p;

            // ---- o += p * v_jj ----
            const float4* vr = (const float4*)&Vs[jj][0];
            #pragma unroll
            for (int d4 = 0; d4 < 16; d4++) {
                float4 vv = vr[d4];
                o[4*d4+0] += p*vv.x;
                o[4*d4+1] += p*vv.y;
                o[4*d4+2] += p*vv.z;
                o[4*d4+3] += p*vv.w;
            }
        }
        __syncthreads();
    }

    const float inv = 1.f / l;
    float* op = out + ((size_t)(b*T_ + t))*C_ + h*D_;
    #pragma unroll
    for (int d4 = 0; d4 < 16; d4++) {
        float4 v;
        v.x = o[4*d4+0]*inv; v.y = o[4*d4+1]*inv;
        v.z = o[4*d4+2]*inv; v.w = o[4*d4+3]*inv;
        *(float4*)(op + 4*d4) = v;
    }
}

// ----------------------------------------------------------------------------
extern "C" void kernel_launch(void* const* d_in, const int* in_sizes, int n_in,
                              void* d_out, int out_size)
{
    const float* x_norm = (const float*)d_in[0];   // (2,2048,1024)
    const float* xt_cur = (const float*)d_in[1];   // (2,2048,1024)
    const float* W_attn = (const float*)d_in[2];   // (1024,2048)
    const float* b_attn = (const float*)d_in[3];   // (2048,)
    float* out = (float*)d_out;

    dim3 g1(N_GEMM/128, M_GEMM/128);   // (16, 32)
    gemm_qk_kernel<<<g1, 256>>>(x_norm, W_attn, b_attn);

    dim3 g2(T_/128, B_*H_);            // (16, 32)
    attn_kernel<<<g2, 128>>>(xt_cur, out);
}

// round 3
// speedup vs baseline: 2.5182x; 2.5182x over previous
#include <cuda_runtime.h>
#include <cuda_fp16.h>
#include <cstdint>

// ============================================================================
// FactoredCausalSelfAttention  (B=2, T=2048, C=1024, H=16, D=64)
// Round 3: split-precision fp16 tensor-core projection (3-pass, ~fp32 exact)
//          + flash attention: QK^T fp16 3-pass, PV tf32 2-pass (V split).
// ============================================================================

#define B_   2
#define T_   2048
#define C_   1024
#define H_   16
#define D_   64
#define BH_  (B_*H_)
#define M_GEMM (B_*T_)      // 4096
#define N_GEMM (2*C_)       // 2048
#define K_GEMM (C_)         // 1024

// ---- device scratch (no allocations allowed) ----
__device__ __align__(16) __half g_Xh [(size_t)M_GEMM*K_GEMM];
__device__ __align__(16) __half g_Xl [(size_t)M_GEMM*K_GEMM];
__device__ __align__(16) __half g_Whi[(size_t)N_GEMM*K_GEMM];  // transposed [n][k]
__device__ __align__(16) __half g_Wlo[(size_t)N_GEMM*K_GEMM];  // transposed [n][k]
__device__ __align__(16) __half g_qh [(size_t)BH_*T_*D_];
__device__ __align__(16) __half g_ql [(size_t)BH_*T_*D_];
__device__ __align__(16) __half g_kh [(size_t)BH_*T_*D_];
__device__ __align__(16) __half g_kl [(size_t)BH_*T_*D_];

// ---------------------------------------------------------------- helpers ---
__device__ __forceinline__ void mma_fp16(float c[4], const uint32_t a[4],
                                         uint32_t b0, uint32_t b1)
{
    asm volatile(
        "mma.sync.aligned.m16n8k16.row.col.f32.f16.f16.f32 "
        "{%0,%1,%2,%3}, {%4,%5,%6,%7}, {%8,%9}, {%0,%1,%2,%3};\n"
        : "+f"(c[0]), "+f"(c[1]), "+f"(c[2]), "+f"(c[3])
        : "r"(a[0]), "r"(a[1]), "r"(a[2]), "r"(a[3]), "r"(b0), "r"(b1));
}

__device__ __forceinline__ void mma_tf32(float c[4],
                                         uint32_t a0, uint32_t a1, uint32_t a2, uint32_t a3,
                                         uint32_t b0, uint32_t b1)
{
    asm volatile(
        "mma.sync.aligned.m16n8k8.row.col.f32.tf32.tf32.f32 "
        "{%0,%1,%2,%3}, {%4,%5,%6,%7}, {%8,%9}, {%0,%1,%2,%3};\n"
        : "+f"(c[0]), "+f"(c[1]), "+f"(c[2]), "+f"(c[3])
        : "r"(a0), "r"(a1), "r"(a2), "r"(a3), "r"(b0), "r"(b1));
}

__device__ __forceinline__ float rna_tf32(float x) {
    uint32_t u;
    asm("cvt.rna.tf32.f32 %0, %1;" : "=r"(u) : "f"(x));
    return __uint_as_float(u);
}

__device__ __forceinline__ float ex2f(float x) {
    float y;
    asm("ex2.approx.f32 %0, %1;" : "=f"(y) : "f"(x));
    return y;
}

__device__ __forceinline__ void cp_async16(uint32_t smem_addr, const void* gptr) {
    asm volatile("cp.async.ca.shared.global [%0], [%1], 16;\n"
                 :: "r"(smem_addr), "l"(gptr));
}
__device__ __forceinline__ void cp_async_commit() {
    asm volatile("cp.async.commit_group;\n");
}
template<int N>
__device__ __forceinline__ void cp_async_wait() {
    asm volatile("cp.async.wait_group %0;\n" :: "n"(N));
}

__device__ __forceinline__ uint32_t f2u(float x) { return __float_as_uint(x); }

// ----------------------------------------------------------------------------
// prep_x: X fp32 -> (Xh, Xl) fp16 split, same layout [m][k]
// ----------------------------------------------------------------------------
__global__ __launch_bounds__(256) void prep_x_kernel(const float* __restrict__ X)
{
    int i = blockIdx.x * 256 + threadIdx.x;        // float2 index, 2M total
    float2 v = ((const float2*)X)[i];
    __half h0 = __float2half_rn(v.x);
    __half h1 = __float2half_rn(v.y);
    ((__half2*)g_Xh)[i] = __halves2half2(h0, h1);
    ((__half2*)g_Xl)[i] = __halves2half2(__float2half_rn(v.x - __half2float(h0)),
                                         __float2half_rn(v.y - __half2float(h1)));
}

// ----------------------------------------------------------------------------
// prep_w: W fp32 [k][n] -> transposed fp16 split (Whi, Wlo) [n][k]
// 32x32 tile transpose, block (32,8), grid (n/32, k/32)
// ----------------------------------------------------------------------------
__global__ __launch_bounds__(256) void prep_w_kernel(const float* __restrict__ W)
{
    __shared__ float t[32][33];
    const int bn = blockIdx.x, bk = blockIdx.y;
    const int tx = threadIdx.x, ty = threadIdx.y;   // 32, 8
    #pragma unroll
    for (int j = 0; j < 4; j++)
        t[ty + 8*j][tx] = W[(size_t)(bk*32 + ty + 8*j) * N_GEMM + bn*32 + tx];
    __syncthreads();
    #pragma unroll
    for (int j = 0; j < 4; j++) {
        const int n = bn*32 + ty + 8*j;
        const int k = bk*32 + tx;
        float v = t[tx][ty + 8*j];
        __half h = __float2half_rn(v);
        g_Whi[(size_t)n * K_GEMM + k] = h;
        g_Wlo[(size_t)n * K_GEMM + k] = __float2half_rn(v - __half2float(h));
    }
}

// ----------------------------------------------------------------------------
// GEMM (fp16 3-pass split): qk = X @ W + bias  -> split-scatter q/k hi/lo fp16
// CTA 128x128, BK=32, 8 warps (4m x 2n), 2-stage cp.async.
// smem halves per stage: Ah[128][40], Al[128][40], Bh[128][40], Bl[128][40]
// ----------------------------------------------------------------------------
#define G_ARR (128*40)                  // halves per array
#define G_STAGE (4*G_ARR)               // 20480 halves
#define GEMM_SMEM_BYTES (2*G_STAGE*2)   // 81920 bytes

__global__ __launch_bounds__(256) void gemm_qk_kernel(const float* __restrict__ bias)
{
    extern __shared__ __half gsm[];

    const int bx = blockIdx.x;     // n-tile (0..15)
    const int by = blockIdx.y;     // m-tile (0..31)
    const int tid = threadIdx.x;
    const int warp = tid >> 5;
    const int lane = tid & 31;
    const int lr = lane >> 2;      // 0..7
    const int lc = lane & 3;       // 0..3
    const int wm = warp >> 1;      // 0..3
    const int wn = warp & 1;       // 0..1

    float c[2][8][4];
    #pragma unroll
    for (int mt = 0; mt < 2; mt++)
        #pragma unroll
        for (int nt = 0; nt < 8; nt++)
            #pragma unroll
            for (int j = 0; j < 4; j++) c[mt][nt][j] = 0.f;

    const uint32_t sm_base = (uint32_t)__cvta_generic_to_shared(gsm);

    auto issue_stage = [&](int stage, int k0) {
        const uint32_t st = sm_base + (uint32_t)(stage * G_STAGE) * 2;
        #pragma unroll
        for (int i = 0; i < 8; i++) {
            int idx = tid + i * 256;          // 0..2047
            int sec = idx >> 9;               // 0:Ah 1:Al 2:Bh 3:Bl
            int sub = idx & 511;
            int r   = sub >> 2;               // 0..127
            int c8  = (sub & 3) * 8;          // half offset in row
            const __half* src;
            if      (sec == 0) src = g_Xh  + (size_t)(by*128 + r) * K_GEMM + k0 + c8;
            else if (sec == 1) src = g_Xl  + (size_t)(by*128 + r) * K_GEMM + k0 + c8;
            else if (sec == 2) src = g_Whi + (size_t)(bx*128 + r) * K_GEMM + k0 + c8;
            else               src = g_Wlo + (size_t)(bx*128 + r) * K_GEMM + k0 + c8;
            cp_async16(st + (uint32_t)(sec * G_ARR + r * 40 + c8) * 2, src);
        }
        cp_async_commit();
    };

    issue_stage(0, 0);

    const int NIT = K_GEMM / 32;   // 32
    for (int it = 0; it < NIT; it++) {
        if (it + 1 < NIT) {
            issue_stage((it + 1) & 1, (it + 1) * 32);
            cp_async_wait<1>();
        } else {
            cp_async_wait<0>();
        }
        __syncthreads();

        const __half* Ah = gsm + (it & 1) * G_STAGE;
        const __half* Al = Ah + G_ARR;
        const __half* Bh = Ah + 2 * G_ARR;
        const __half* Bl = Ah + 3 * G_ARR;

        #pragma unroll
        for (int ks = 0; ks < 2; ks++) {
            uint32_t ah[2][4], al[2][4];
            #pragma unroll
            for (int mt = 0; mt < 2; mt++) {
                const int rb = (wm*32 + mt*16) * 40 + 16*ks + 2*lc;
                ah[mt][0] = *(const uint32_t*)&Ah[rb + lr*40];
                ah[mt][1] = *(const uint32_t*)&Ah[rb + (lr+8)*40];
                ah[mt][2] = *(const uint32_t*)&Ah[rb + lr*40 + 8];
                ah[mt][3] = *(const uint32_t*)&Ah[rb + (lr+8)*40 + 8];
                al[mt][0] = *(const uint32_t*)&Al[rb + lr*40];
                al[mt][1] = *(const uint32_t*)&Al[rb + (lr+8)*40];
                al[mt][2] = *(const uint32_t*)&Al[rb + lr*40 + 8];
                al[mt][3] = *(const uint32_t*)&Al[rb + (lr+8)*40 + 8];
            }
            #pragma unroll
            for (int nt = 0; nt < 8; nt++) {
                const int nb = (wn*64 + nt*8 + lr) * 40 + 16*ks + 2*lc;
                uint32_t bh0 = *(const uint32_t*)&Bh[nb];
                uint32_t bh1 = *(const uint32_t*)&Bh[nb + 8];
                uint32_t bl0 = *(const uint32_t*)&Bl[nb];
                uint32_t bl1 = *(const uint32_t*)&Bl[nb + 8];
                #pragma unroll
                for (int mt = 0; mt < 2; mt++) {
                    mma_fp16(c[mt][nt], ah[mt], bh0, bh1);
                    mma_fp16(c[mt][nt], ah[mt], bl0, bl1);
                    mma_fp16(c[mt][nt], al[mt], bh0, bh1);
                }
            }
        }
        __syncthreads();
    }

    // epilogue: bias + split-scatter into head-transposed fp16 q/k (hi/lo)
    #pragma unroll
    for (int mt = 0; mt < 2; mt++) {
        #pragma unroll
        for (int rr = 0; rr < 2; rr++) {
            const int m = by*128 + wm*32 + mt*16 + rr*8 + lr;
            const int b = m >> 11;
            const int t = m & (T_ - 1);
            #pragma unroll
            for (int nt = 0; nt < 8; nt++) {
                const int n0 = bx*128 + wn*64 + nt*8 + 2*lc;
                const float v0 = c[mt][nt][rr*2 + 0] + bias[n0];
                const float v1 = c[mt][nt][rr*2 + 1] + bias[n0 + 1];
                __half h0 = __float2half_rn(v0);
                __half h1 = __float2half_rn(v1);
                __half l0 = __float2half_rn(v0 - __half2float(h0));
                __half l1 = __float2half_rn(v1 - __half2float(h1));
                if (n0 < C_) {
                    const int hh = n0 >> 6, d = n0 & 63;
                    const size_t o = (((size_t)(b*H_ + hh)) * T_ + t) * D_ + d;
                    *(__half2*)&g_qh[o] = __halves2half2(h0, h1);
                    *(__half2*)&g_ql[o] = __halves2half2(l0, l1);
                } else {
                    const int n2 = n0 - C_;
                    const int hh = n2 >> 6, d = n2 & 63;
                    const size_t o = (((size_t)(b*H_ + hh)) * T_ + t) * D_ + d;
                    *(__half2*)&g_kh[o] = __halves2half2(h0, h1);
                    *(__half2*)&g_kl[o] = __halves2half2(l0, l1);
                }
            }
        }
    }
}

// ----------------------------------------------------------------------------
// Flash attention (causal): QK^T fp16 3-pass split, PV tf32 2-pass (V split).
// 8 warps x 16 q-rows = 128 rows/CTA; KV tiles of 64.
// smem bytes:
//   [0      : 9216 )  Khi half [64][72]
//   [9216   : 18432)  Klo half [64][72]
//   [18432  : 36864)  Vh  f32  [64][72]
//   [36864  : 55296)  Vl  f32  [64][72]
//   [55296  : 92160)  P f32 [128][68] / Q staging (Qh,Ql half [128][72])
// ----------------------------------------------------------------------------
#define ATTN_SMEM_BYTES 92160

__global__ __launch_bounds__(256) void attn_kernel(
    const float* __restrict__ xt,   // [B,T,C] -> v
    float* __restrict__ out)        // [B,T,C]
{
    extern __shared__ char smraw[];
    __half* Khi = (__half*)smraw;
    __half* Klo = Khi + 64*72;
    float*  Vh  = (float*)(smraw + 18432);
    float*  Vl  = Vh + 64*72;
    float*  Ps  = (float*)(smraw + 55296);
    __half* Qhs = (__half*)(smraw + 55296);
    __half* Qls = Qhs + 128*72;

    const int bh = blockIdx.y;
    const int b  = bh >> 4;
    const int h  = bh & 15;
    const int tid  = threadIdx.x;
    const int warp = tid >> 5;
    const int lane = tid & 31;
    const int lr = lane >> 2;
    const int lc = lane & 3;
    const int qt = gridDim.x - 1 - blockIdx.x;    // heavy tiles first
    const int t0 = qt * 128;

    // ---- stage Q hi/lo tiles, build register-resident A fragments ----
    #pragma unroll
    for (int i = 0; i < 4; i++) {
        int idx = tid + i * 256;          // 0..1023
        int r = idx >> 3, c8 = (idx & 7) * 8;
        *(float4*)&Qhs[r*72 + c8] =
            *(const float4*)(g_qh + ((size_t)bh*T_ + t0 + r)*D_ + c8);
        *(float4*)&Qls[r*72 + c8] =
            *(const float4*)(g_ql + ((size_t)bh*T_ + t0 + r)*D_ + c8);
    }
    __syncthreads();

    uint32_t qfh[4][4], qfl[4][4];
    {
        const int r0 = (warp*16 + lr) * 72;
        const int r1 = r0 + 8*72;
        #pragma unroll
        for (int ks = 0; ks < 4; ks++) {
            const int cc = 16*ks + 2*lc;
            qfh[ks][0] = *(const uint32_t*)&Qhs[r0 + cc];
            qfh[ks][1] = *(const uint32_t*)&Qhs[r1 + cc];
            qfh[ks][2] = *(const uint32_t*)&Qhs[r0 + cc + 8];
            qfh[ks][3] = *(const uint32_t*)&Qhs[r1 + cc + 8];
            qfl[ks][0] = *(const uint32_t*)&Qls[r0 + cc];
            qfl[ks][1] = *(const uint32_t*)&Qls[r1 + cc];
            qfl[ks][2] = *(const uint32_t*)&Qls[r0 + cc + 8];
            qfl[ks][3] = *(const uint32_t*)&Qls[r1 + cc + 8];
        }
    }

    float o[8][4];
    #pragma unroll
    for (int dt = 0; dt < 8; dt++)
        #pragma unroll
        for (int j = 0; j < 4; j++) o[dt][j] = 0.f;

    float m0 = -1e30f, m1 = -1e30f;
    float l0 = 0.f, l1 = 0.f;
    const float C2 = 0.125f * 1.44269504089f;   // scale * log2(e)

    const int rg0 = t0 + warp*16 + lr;
    const int rg1 = rg0 + 8;
    const int prow0 = (warp*16 + lr) * 68;
    const int prow1 = prow0 + 8*68;

    for (int j0 = 0; j0 <= t0 + 64; j0 += 64) {
        __syncthreads();   // previous tile reads (and Q staging) complete
        // ---- load K hi/lo (half) and V (split tf32) tiles ----
        #pragma unroll
        for (int i = 0; i < 2; i++) {
            int idx = tid + i * 256;      // 0..511
            int r = idx >> 3, c8 = (idx & 7) * 8;
            *(float4*)&Khi[r*72 + c8] =
                *(const float4*)(g_kh + ((size_t)bh*T_ + j0 + r)*D_ + c8);
            *(float4*)&Klo[r*72 + c8] =
                *(const float4*)(g_kl + ((size_t)bh*T_ + j0 + r)*D_ + c8);
        }
        #pragma unroll
        for (int i = 0; i < 4; i++) {
            int idx = tid + i * 256;      // 0..1023
            int r = idx >> 4, c4 = (idx & 15) * 4;
            float4 v = *(const float4*)(xt + ((size_t)(b*T_ + j0 + r))*C_ + h*D_ + c4);
            float4 vh, vl;
            vh.x = rna_tf32(v.x); vl.x = rna_tf32(v.x - vh.x);
            vh.y = rna_tf32(v.y); vl.y = rna_tf32(v.y - vh.y);
            vh.z = rna_tf32(v.z); vl.z = rna_tf32(v.z - vh.z);
            vh.w = rna_tf32(v.w); vl.w = rna_tf32(v.w - vh.w);
            *(float4*)&Vh[r*72 + c4] = vh;
            *(float4*)&Vl[r*72 + c4] = vl;
        }
        __syncthreads();

        // ---- S = Q K^T  (fp16, 3-pass split) ----
        float s[8][4];
        #pragma unroll
        for (int nt = 0; nt < 8; nt++)
            #pragma unroll
            for (int j = 0; j < 4; j++) s[nt][j] = 0.f;

        #pragma unroll
        for (int ks = 0; ks < 4; ks++) {
            #pragma unroll
            for (int nt = 0; nt < 8; nt++) {
                const int kr = (nt*8 + lr)*72 + 16*ks + 2*lc;
                uint32_t bh0 = *(const uint32_t*)&Khi[kr];
                uint32_t bh1 = *(const uint32_t*)&Khi[kr + 8];
                uint32_t bl0 = *(const uint32_t*)&Klo[kr];
                uint32_t bl1 = *(const uint32_t*)&Klo[kr + 8];
                mma_fp16(s[nt], qfh[ks], bh0, bh1);
                mma_fp16(s[nt], qfh[ks], bl0, bl1);
                mma_fp16(s[nt], qfl[ks], bh0, bh1);
            }
        }

        // ---- causal mask ----
        if (j0 + 63 > t0) {
            #pragma unroll
            for (int nt = 0; nt < 8; nt++) {
                int cg = j0 + nt*8 + 2*lc;
                if (cg     > rg0) s[nt][0] = -1e30f;
                if (cg + 1 > rg0) s[nt][1] = -1e30f;
                if (cg     > rg1) s[nt][2] = -1e30f;
                if (cg + 1 > rg1) s[nt][3] = -1e30f;
            }
        }

        // ---- online softmax ----
        float t0m = -1e30f, t1m = -1e30f;
        #pragma unroll
        for (int nt = 0; nt < 8; nt++) {
            t0m = fmaxf(t0m, fmaxf(s[nt][0], s[nt][1]));
            t1m = fmaxf(t1m, fmaxf(s[nt][2], s[nt][3]));
        }
        t0m = fmaxf(t0m, __shfl_xor_sync(0xffffffffu, t0m, 1));
        t0m = fmaxf(t0m, __shfl_xor_sync(0xffffffffu, t0m, 2));
        t1m = fmaxf(t1m, __shfl_xor_sync(0xffffffffu, t1m, 1));
        t1m = fmaxf(t1m, __shfl_xor_sync(0xffffffffu, t1m, 2));

        const float mn0 = fmaxf(m0, t0m);
        const float mn1 = fmaxf(m1, t1m);
        const float a0 = ex2f((m0 - mn0) * C2);
        const float a1 = ex2f((m1 - mn1) * C2);
        m0 = mn0; m1 = mn1;
        l0 *= a0; l1 *= a1;
        #pragma unroll
        for (int dt = 0; dt < 8; dt++) {
            o[dt][0] *= a0; o[dt][1] *= a0;
            o[dt][2] *= a1; o[dt][3] *= a1;
        }

        // p rounded (RNA) to tf32, used consistently in l and numerator
        #pragma unroll
        for (int nt = 0; nt < 8; nt++) {
            float p0 = rna_tf32(ex2f((s[nt][0] - m0) * C2));
            float p1 = rna_tf32(ex2f((s[nt][1] - m0) * C2));
            float p2 = rna_tf32(ex2f((s[nt][2] - m1) * C2));
            float p3 = rna_tf32(ex2f((s[nt][3] - m1) * C2));
            l0 += p0 + p1;
            l1 += p2 + p3;
            *(float2*)&Ps[prow0 + nt*8 + 2*lc] = make_float2(p0, p1);
            *(float2*)&Ps[prow1 + nt*8 + 2*lc] = make_float2(p2, p3);
        }
        __syncwarp();   // P rows are per-warp private

        // ---- O += P V  (tf32, 2-pass on split V) ----
        #pragma unroll
        for (int ks = 0; ks < 8; ks++) {
            const uint32_t pa0 = f2u(Ps[prow0 + ks*8 + lc    ]);
            const uint32_t pa1 = f2u(Ps[prow1 + ks*8 + lc    ]);
            const uint32_t pa2 = f2u(Ps[prow0 + ks*8 + lc + 4]);
            const uint32_t pa3 = f2u(Ps[prow1 + ks*8 + lc + 4]);
            #pragma unroll
            for (int dt = 0; dt < 8; dt++) {
                const int v0 = (ks*8 + lc    )*72 + dt*8 + lr;
                const int v1 = (ks*8 + lc + 4)*72 + dt*8 + lr;
                mma_tf32(o[dt], pa0, pa1, pa2, pa3, f2u(Vh[v0]), f2u(Vh[v1]));
                mma_tf32(o[dt], pa0, pa1, pa2, pa3, f2u(Vl[v0]), f2u(Vl[v1]));
            }
        }
        __syncwarp();
    }

    // ---- finalize ----
    l0 += __shfl_xor_sync(0xffffffffu, l0, 1);
    l0 += __shfl_xor_sync(0xffffffffu, l0, 2);
    l1 += __shfl_xor_sync(0xffffffffu, l1, 1);
    l1 += __shfl_xor_sync(0xffffffffu, l1, 2);
    const float inv0 = 1.f / l0;
    const float inv1 = 1.f / l1;

    float* out0 = out + ((size_t)(b*T_ + rg0))*C_ + h*D_;
    float* out1 = out + ((size_t)(b*T_ + rg1))*C_ + h*D_;
    #pragma unroll
    for (int dt = 0; dt < 8; dt++) {
        *(float2*)(out0 + dt*8 + 2*lc) = make_float2(o[dt][0]*inv0, o[dt][1]*inv0);
        *(float2*)(out1 + dt*8 + 2*lc) = make_float2(o[dt][2]*inv1, o[dt][3]*inv1);
    }
}

// ----------------------------------------------------------------------------
extern "C" void kernel_launch(void* const* d_in, const int* in_sizes, int n_in,
                              void* d_out, int out_size)
{
    const float* x_norm = (const float*)d_in[0];   // (2,2048,1024)
    const float* xt_cur = (const float*)d_in[1];   // (2,2048,1024)
    const float* W_attn = (const float*)d_in[2];   // (1024,2048)
    const float* b_attn = (const float*)d_in[3];   // (2048,)
    float* out = (float*)d_out;

    cudaFuncSetAttribute(gemm_qk_kernel,
                         cudaFuncAttributeMaxDynamicSharedMemorySize, GEMM_SMEM_BYTES);
    cudaFuncSetAttribute(attn_kernel,
                         cudaFuncAttributeMaxDynamicSharedMemorySize, ATTN_SMEM_BYTES);

    prep_x_kernel<<<(M_GEMM*K_GEMM/2)/256, 256>>>(x_norm);
    prep_w_kernel<<<dim3(N_GEMM/32, K_GEMM/32), dim3(32, 8)>>>(W_attn);

    dim3 g1(N_GEMM/128, M_GEMM/128);   // (16, 32)
    gemm_qk_kernel<<<g1, 256, GEMM_SMEM_BYTES>>>(b_attn);

    dim3 g2(T_/128, B_*H_);            // (16, 32)
    attn_kernel<<<g2, 256, ATTN_SMEM_BYTES>>>(xt_cur, out);
}

// round 4
// speedup vs baseline: 3.1586x; 1.2543x over previous
#include <cuda_runtime.h>
#include <cuda_fp16.h>
#include <cstdint>

// ============================================================================
// FactoredCausalSelfAttention  (B=2, T=2048, C=1024, H=16, D=64)
// Round 4: all-fp16 split-precision tensor cores.
//   - projection: fp16 3-pass (as round 3)
//   - attention: QK^T fp16 3-pass; PV fp16 3-pass with split-P and
//     precomputed split-V (head-transposed [bh][d][t]); cp.async
//     double-buffered KV tiles.
// ============================================================================

#define B_   2
#define T_   2048
#define C_   1024
#define H_   16
#define D_   64
#define BH_  (B_*H_)
#define M_GEMM (B_*T_)      // 4096
#define N_GEMM (2*C_)       // 2048
#define K_GEMM (C_)         // 1024

// ---- device scratch (no allocations allowed) ----
__device__ __align__(16) __half g_Xh [(size_t)M_GEMM*K_GEMM];
__device__ __align__(16) __half g_Xl [(size_t)M_GEMM*K_GEMM];
__device__ __align__(16) __half g_Whi[(size_t)N_GEMM*K_GEMM];  // [n][k]
__device__ __align__(16) __half g_Wlo[(size_t)N_GEMM*K_GEMM];  // [n][k]
__device__ __align__(16) __half g_qh [(size_t)BH_*T_*D_];      // [bh][t][d]
__device__ __align__(16) __half g_ql [(size_t)BH_*T_*D_];
__device__ __align__(16) __half g_kh [(size_t)BH_*T_*D_];
__device__ __align__(16) __half g_kl [(size_t)BH_*T_*D_];
__device__ __align__(16) __half g_vh [(size_t)BH_*D_*T_];      // [bh][d][t]
__device__ __align__(16) __half g_vl [(size_t)BH_*D_*T_];

// ---------------------------------------------------------------- helpers ---
__device__ __forceinline__ void mma_fp16(float c[4], const uint32_t a[4],
                                         uint32_t b0, uint32_t b1)
{
    asm volatile(
        "mma.sync.aligned.m16n8k16.row.col.f32.f16.f16.f32 "
        "{%0,%1,%2,%3}, {%4,%5,%6,%7}, {%8,%9}, {%0,%1,%2,%3};\n"
        : "+f"(c[0]), "+f"(c[1]), "+f"(c[2]), "+f"(c[3])
        : "r"(a[0]), "r"(a[1]), "r"(a[2]), "r"(a[3]), "r"(b0), "r"(b1));
}

__device__ __forceinline__ float ex2f(float x) {
    float y;
    asm("ex2.approx.f32 %0, %1;" : "=f"(y) : "f"(x));
    return y;
}

__device__ __forceinline__ void cp_async16(uint32_t smem_addr, const void* gptr) {
    asm volatile("cp.async.ca.shared.global [%0], [%1], 16;\n"
                 :: "r"(smem_addr), "l"(gptr));
}
__device__ __forceinline__ void cp_async_commit() {
    asm volatile("cp.async.commit_group;\n");
}
template<int N>
__device__ __forceinline__ void cp_async_wait() {
    asm volatile("cp.async.wait_group %0;\n" :: "n"(N));
}

// ----------------------------------------------------------------------------
// prep_x: X fp32 -> (Xh, Xl) fp16 split, layout [m][k]
// ----------------------------------------------------------------------------
__global__ __launch_bounds__(256) void prep_x_kernel(const float* __restrict__ X)
{
    int i = blockIdx.x * 256 + threadIdx.x;        // float2 index
    float2 v = ((const float2*)X)[i];
    __half h0 = __float2half_rn(v.x);
    __half h1 = __float2half_rn(v.y);
    ((__half2*)g_Xh)[i] = __halves2half2(h0, h1);
    ((__half2*)g_Xl)[i] = __halves2half2(__float2half_rn(v.x - __half2float(h0)),
                                         __float2half_rn(v.y - __half2float(h1)));
}

// ----------------------------------------------------------------------------
// prep_w: W fp32 [k][n] -> transposed fp16 split (Whi, Wlo) [n][k]
// ----------------------------------------------------------------------------
__global__ __launch_bounds__(256) void prep_w_kernel(const float* __restrict__ W)
{
    __shared__ float t[32][33];
    const int bn = blockIdx.x, bk = blockIdx.y;
    const int tx = threadIdx.x, ty = threadIdx.y;   // 32, 8
    #pragma unroll
    for (int j = 0; j < 4; j++)
        t[ty + 8*j][tx] = W[(size_t)(bk*32 + ty + 8*j) * N_GEMM + bn*32 + tx];
    __syncthreads();
    #pragma unroll
    for (int j = 0; j < 4; j++) {
        const int n = bn*32 + ty + 8*j;
        const int k = bk*32 + tx;
        float v = t[tx][ty + 8*j];
        __half h = __float2half_rn(v);
        g_Whi[(size_t)n * K_GEMM + k] = h;
        g_Wlo[(size_t)n * K_GEMM + k] = __float2half_rn(v - __half2float(h));
    }
}

// ----------------------------------------------------------------------------
// prep_v: xt fp32 [b][t][c] -> fp16 split (vh, vl) head-transposed [bh][d][t]
// grid (T/32, D/32, BH), block (32,8); smem tile transpose
// ----------------------------------------------------------------------------
__global__ __launch_bounds__(256) void prep_v_kernel(const float* __restrict__ xt)
{
    __shared__ float t[32][33];
    const int bh = blockIdx.z;
    const int b = bh >> 4, h = bh & 15;
    const int tt = blockIdx.x * 32;
    const int dd = blockIdx.y * 32;
    const int tx = threadIdx.x, ty = threadIdx.y;
    #pragma unroll
    for (int j = 0; j < 4; j++)
        t[ty + 8*j][tx] = xt[(size_t)(b*T_ + tt + ty + 8*j) * C_ + h*D_ + dd + tx];
    __syncthreads();
    #pragma unroll
    for (int j = 0; j < 4; j++) {
        const int d = dd + ty + 8*j;
        float v = t[tx][ty + 8*j];
        __half hh = __float2half_rn(v);
        const size_t o = ((size_t)bh*D_ + d) * T_ + tt + tx;
        g_vh[o] = hh;
        g_vl[o] = __float2half_rn(v - __half2float(hh));
    }
}

// ----------------------------------------------------------------------------
// GEMM (fp16 3-pass): qk = X @ W + bias -> split-scatter q/k hi/lo fp16
// ----------------------------------------------------------------------------
#define G_ARR (128*40)
#define G_STAGE (4*G_ARR)
#define GEMM_SMEM_BYTES (2*G_STAGE*2)   // 81920

__global__ __launch_bounds__(256, 2) void gemm_qk_kernel(const float* __restrict__ bias)
{
    extern __shared__ __half gsm[];

    const int bx = blockIdx.x;
    const int by = blockIdx.y;
    const int tid = threadIdx.x;
    const int warp = tid >> 5;
    const int lane = tid & 31;
    const int lr = lane >> 2;
    const int lc = lane & 3;
    const int wm = warp >> 1;
    const int wn = warp & 1;

    float c[2][8][4];
    #pragma unroll
    for (int mt = 0; mt < 2; mt++)
        #pragma unroll
        for (int nt = 0; nt < 8; nt++)
            #pragma unroll
            for (int j = 0; j < 4; j++) c[mt][nt][j] = 0.f;

    const uint32_t sm_base = (uint32_t)__cvta_generic_to_shared(gsm);

    auto issue_stage = [&](int stage, int k0) {
        const uint32_t st = sm_base + (uint32_t)(stage * G_STAGE) * 2;
        #pragma unroll
        for (int i = 0; i < 8; i++) {
            int idx = tid + i * 256;
            int sec = idx >> 9;
            int sub = idx & 511;
            int r   = sub >> 2;
            int c8  = (sub & 3) * 8;
            const __half* src;
            if      (sec == 0) src = g_Xh  + (size_t)(by*128 + r) * K_GEMM + k0 + c8;
            else if (sec == 1) src = g_Xl  + (size_t)(by*128 + r) * K_GEMM + k0 + c8;
            else if (sec == 2) src = g_Whi + (size_t)(bx*128 + r) * K_GEMM + k0 + c8;
            else               src = g_Wlo + (size_t)(bx*128 + r) * K_GEMM + k0 + c8;
            cp_async16(st + (uint32_t)(sec * G_ARR + r * 40 + c8) * 2, src);
        }
        cp_async_commit();
    };

    issue_stage(0, 0);

    const int NIT = K_GEMM / 32;
    for (int it = 0; it < NIT; it++) {
        if (it + 1 < NIT) {
            issue_stage((it + 1) & 1, (it + 1) * 32);
            cp_async_wait<1>();
        } else {
            cp_async_wait<0>();
        }
        __syncthreads();

        const __half* Ah = gsm + (it & 1) * G_STAGE;
        const __half* Al = Ah + G_ARR;
        const __half* Bh = Ah + 2 * G_ARR;
        const __half* Bl = Ah + 3 * G_ARR;

        #pragma unroll
        for (int ks = 0; ks < 2; ks++) {
            uint32_t ah[2][4], al[2][4];
            #pragma unroll
            for (int mt = 0; mt < 2; mt++) {
                const int rb = (wm*32 + mt*16) * 40 + 16*ks + 2*lc;
                ah[mt][0] = *(const uint32_t*)&Ah[rb + lr*40];
                ah[mt][1] = *(const uint32_t*)&Ah[rb + (lr+8)*40];
                ah[mt][2] = *(const uint32_t*)&Ah[rb + lr*40 + 8];
                ah[mt][3] = *(const uint32_t*)&Ah[rb + (lr+8)*40 + 8];
                al[mt][0] = *(const uint32_t*)&Al[rb + lr*40];
                al[mt][1] = *(const uint32_t*)&Al[rb + (lr+8)*40];
                al[mt][2] = *(const uint32_t*)&Al[rb + lr*40 + 8];
                al[mt][3] = *(const uint32_t*)&Al[rb + (lr+8)*40 + 8];
            }
            #pragma unroll
            for (int nt = 0; nt < 8; nt++) {
                const int nb = (wn*64 + nt*8 + lr) * 40 + 16*ks + 2*lc;
                uint32_t bh0 = *(const uint32_t*)&Bh[nb];
                uint32_t bh1 = *(const uint32_t*)&Bh[nb + 8];
                uint32_t bl0 = *(const uint32_t*)&Bl[nb];
                uint32_t bl1 = *(const uint32_t*)&Bl[nb + 8];
                #pragma unroll
                for (int mt = 0; mt < 2; mt++) {
                    mma_fp16(c[mt][nt], ah[mt], bh0, bh1);
                    mma_fp16(c[mt][nt], ah[mt], bl0, bl1);
                    mma_fp16(c[mt][nt], al[mt], bh0, bh1);
                }
            }
        }
        __syncthreads();
    }

    #pragma unroll
    for (int mt = 0; mt < 2; mt++) {
        #pragma unroll
        for (int rr = 0; rr < 2; rr++) {
            const int m = by*128 + wm*32 + mt*16 + rr*8 + lr;
            const int b = m >> 11;
            const int t = m & (T_ - 1);
            #pragma unroll
            for (int nt = 0; nt < 8; nt++) {
                const int n0 = bx*128 + wn*64 + nt*8 + 2*lc;
                const float v0 = c[mt][nt][rr*2 + 0] + bias[n0];
                const float v1 = c[mt][nt][rr*2 + 1] + bias[n0 + 1];
                __half h0 = __float2half_rn(v0);
                __half h1 = __float2half_rn(v1);
                __half l0 = __float2half_rn(v0 - __half2float(h0));
                __half l1 = __float2half_rn(v1 - __half2float(h1));
                if (n0 < C_) {
                    const int hh = n0 >> 6, d = n0 & 63;
                    const size_t o = (((size_t)(b*H_ + hh)) * T_ + t) * D_ + d;
                    *(__half2*)&g_qh[o] = __halves2half2(h0, h1);
                    *(__half2*)&g_ql[o] = __halves2half2(l0, l1);
                } else {
                    const int n2 = n0 - C_;
                    const int hh = n2 >> 6, d = n2 & 63;
                    const size_t o = (((size_t)(b*H_ + hh)) * T_ + t) * D_ + d;
                    *(__half2*)&g_kh[o] = __halves2half2(h0, h1);
                    *(__half2*)&g_kl[o] = __halves2half2(l0, l1);
                }
            }
        }
    }
}

// ----------------------------------------------------------------------------
// Flash attention (causal): all fp16 mma, split-precision.
//   QK^T: qh*kh + qh*kl + ql*kh        (3-pass)
//   PV  : ph*vh + ph*vl + pl*vh        (3-pass, split-P exact to ~2^-21)
// cp.async double-buffered KV tiles (64 kv x 64 d, all fp16).
// smem (bytes):
//   stage s in {0,1} at s*36864:
//     Khi half[64][72] @ +0      Klo @ +9216
//     Vh  half[64][72] @ +18432  Vl  @ +27648   (V rows = d, cols = kv)
//   P/Q region @ 73728:
//     Ph half[128][72] / Qh staging;  Pl @ +18432 / Ql staging
// total 110592
// ----------------------------------------------------------------------------
#define A_STAGE 36864
#define A_PQ    73728
#define ATTN_SMEM_BYTES 110592

__global__ __launch_bounds__(256) void attn_kernel(float* __restrict__ out)
{
    extern __shared__ char smraw[];
    const uint32_t sm_base = (uint32_t)__cvta_generic_to_shared(smraw);
    __half* Ph  = (__half*)(smraw + A_PQ);
    __half* Pl  = Ph + 128*72;
    __half* Qhs = Ph;               // staging aliases P region
    __half* Qls = Pl;

    const int bh = blockIdx.y;
    const int b  = bh >> 4;
    const int h  = bh & 15;
    const int tid  = threadIdx.x;
    const int warp = tid >> 5;
    const int lane = tid & 31;
    const int lr = lane >> 2;
    const int lc = lane & 3;
    const int qt = gridDim.x - 1 - blockIdx.x;    // heavy tiles first
    const int t0 = qt * 128;

    // ---- stage Q hi/lo, build register-resident A fragments ----
    #pragma unroll
    for (int i = 0; i < 4; i++) {
        int idx = tid + i * 256;          // 0..1023
        int r = idx >> 3, c8 = (idx & 7) * 8;
        *(float4*)&Qhs[r*72 + c8] =
            *(const float4*)(g_qh + ((size_t)bh*T_ + t0 + r)*D_ + c8);
        *(float4*)&Qls[r*72 + c8] =
            *(const float4*)(g_ql + ((size_t)bh*T_ + t0 + r)*D_ + c8);
    }
    __syncthreads();

    uint32_t qfh[4][4], qfl[4][4];
    {
        const int r0 = (warp*16 + lr) * 72;
        const int r1 = r0 + 8*72;
        #pragma unroll
        for (int ks = 0; ks < 4; ks++) {
            const int cc = 16*ks + 2*lc;
            qfh[ks][0] = *(const uint32_t*)&Qhs[r0 + cc];
            qfh[ks][1] = *(const uint32_t*)&Qhs[r1 + cc];
            qfh[ks][2] = *(const uint32_t*)&Qhs[r0 + cc + 8];
            qfh[ks][3] = *(const uint32_t*)&Qhs[r1 + cc + 8];
            qfl[ks][0] = *(const uint32_t*)&Qls[r0 + cc];
            qfl[ks][1] = *(const uint32_t*)&Qls[r1 + cc];
            qfl[ks][2] = *(const uint32_t*)&Qls[r0 + cc + 8];
            qfl[ks][3] = *(const uint32_t*)&Qls[r1 + cc + 8];
        }
    }

    float o[8][4];
    #pragma unroll
    for (int dt = 0; dt < 8; dt++)
        #pragma unroll
        for (int j = 0; j < 4; j++) o[dt][j] = 0.f;

    float m0 = -1e30f, m1 = -1e30f;
    float l0 = 0.f, l1 = 0.f;
    const float C2 = 0.125f * 1.44269504089f;

    const int rg0 = t0 + warp*16 + lr;
    const int rg1 = rg0 + 8;
    const int prow0 = (warp*16 + lr) * 72;
    const int prow1 = prow0 + 8*72;

    // ---- cp.async tile loader: Khi,Klo [kv][d]; Vh,Vl [d][kv] ----
    auto issue_tile = [&](int stage, int j0) {
        const uint32_t st = sm_base + (uint32_t)stage * A_STAGE;
        #pragma unroll
        for (int i = 0; i < 8; i++) {
            int idx = tid + i * 256;      // 0..2047
            int sec = idx >> 9;           // 0:Khi 1:Klo 2:Vh 3:Vl
            int sub = idx & 511;
            int r   = sub >> 3;           // 0..63
            int c8  = (sub & 7) * 8;
            const __half* src;
            if      (sec == 0) src = g_kh + ((size_t)bh*T_ + j0 + r)*D_ + c8;
            else if (sec == 1) src = g_kl + ((size_t)bh*T_ + j0 + r)*D_ + c8;
            else if (sec == 2) src = g_vh + ((size_t)bh*D_ + r)*T_ + j0 + c8;
            else               src = g_vl + ((size_t)bh*D_ + r)*T_ + j0 + c8;
            cp_async16(st + (uint32_t)(sec * 9216) + (uint32_t)(r*72 + c8)*2, src);
        }
        cp_async_commit();
    };

    const int ntiles = 2*qt + 2;
    issue_tile(0, 0);

    for (int it = 0; it < ntiles; it++) {
        const int j0 = it * 64;
        if (it + 1 < ntiles) {
            issue_tile((it + 1) & 1, (it + 1) * 64);
            cp_async_wait<1>();
        } else {
            cp_async_wait<0>();
        }
        __syncthreads();

        const __half* Khi = (const __half*)(smraw + (it & 1) * A_STAGE);
        const __half* Klo = Khi + 64*72;
        const __half* Vh  = Khi + 2*64*72;
        const __half* Vl  = Khi + 3*64*72;

        // ---- S = Q K^T  (fp16 3-pass) ----
        float s[8][4];
        #pragma unroll
        for (int nt = 0; nt < 8; nt++)
            #pragma unroll
            for (int j = 0; j < 4; j++) s[nt][j] = 0.f;

        #pragma unroll
        for (int ks = 0; ks < 4; ks++) {
            #pragma unroll
            for (int nt = 0; nt < 8; nt++) {
                const int kr = (nt*8 + lr)*72 + 16*ks + 2*lc;
                uint32_t bh0 = *(const uint32_t*)&Khi[kr];
                uint32_t bh1 = *(const uint32_t*)&Khi[kr + 8];
                uint32_t bl0 = *(const uint32_t*)&Klo[kr];
                uint32_t bl1 = *(const uint32_t*)&Klo[kr + 8];
                mma_fp16(s[nt], qfh[ks], bh0, bh1);
                mma_fp16(s[nt], qfh[ks], bl0, bl1);
                mma_fp16(s[nt], qfl[ks], bh0, bh1);
            }
        }

        // ---- causal mask ----
        if (j0 + 63 > t0) {
            #pragma unroll
            for (int nt = 0; nt < 8; nt++) {
                int cg = j0 + nt*8 + 2*lc;
                if (cg     > rg0) s[nt][0] = -1e30f;
                if (cg + 1 > rg0) s[nt][1] = -1e30f;
                if (cg     > rg1) s[nt][2] = -1e30f;
                if (cg + 1 > rg1) s[nt][3] = -1e30f;
            }
        }

        // ---- online softmax ----
        float t0m = -1e30f, t1m = -1e30f;
        #pragma unroll
        for (int nt = 0; nt < 8; nt++) {
            t0m = fmaxf(t0m, fmaxf(s[nt][0], s[nt][1]));
            t1m = fmaxf(t1m, fmaxf(s[nt][2], s[nt][3]));
        }
        t0m = fmaxf(t0m, __shfl_xor_sync(0xffffffffu, t0m, 1));
        t0m = fmaxf(t0m, __shfl_xor_sync(0xffffffffu, t0m, 2));
        t1m = fmaxf(t1m, __shfl_xor_sync(0xffffffffu, t1m, 1));
        t1m = fmaxf(t1m, __shfl_xor_sync(0xffffffffu, t1m, 2));

        const float mn0 = fmaxf(m0, t0m);
        const float mn1 = fmaxf(m1, t1m);
        const float a0 = ex2f((m0 - mn0) * C2);
        const float a1 = ex2f((m1 - mn1) * C2);
        m0 = mn0; m1 = mn1;
        l0 *= a0; l1 *= a1;
        #pragma unroll
        for (int dt = 0; dt < 8; dt++) {
            o[dt][0] *= a0; o[dt][1] *= a0;
            o[dt][2] *= a1; o[dt][3] *= a1;
        }

        // ---- p = exp2(...) split into fp16 hi/lo; l in fp32 ----
        #pragma unroll
        for (int nt = 0; nt < 8; nt++) {
            float p0 = ex2f((s[nt][0] - m0) * C2);
            float p1 = ex2f((s[nt][1] - m0) * C2);
            float p2 = ex2f((s[nt][2] - m1) * C2);
            float p3 = ex2f((s[nt][3] - m1) * C2);
            l0 += p0 + p1;
            l1 += p2 + p3;
            __half h0 = __float2half_rn(p0), h1 = __float2half_rn(p1);
            __half h2 = __float2half_rn(p2), h3 = __float2half_rn(p3);
            *(__half2*)&Ph[prow0 + nt*8 + 2*lc] = __halves2half2(h0, h1);
            *(__half2*)&Ph[prow1 + nt*8 + 2*lc] = __halves2half2(h2, h3);
            *(__half2*)&Pl[prow0 + nt*8 + 2*lc] =
                __halves2half2(__float2half_rn(p0 - __half2float(h0)),
                               __float2half_rn(p1 - __half2float(h1)));
            *(__half2*)&Pl[prow1 + nt*8 + 2*lc] =
                __halves2half2(__float2half_rn(p2 - __half2float(h2)),
                               __float2half_rn(p3 - __half2float(h3)));
        }
        __syncwarp();   // P rows are per-warp private

        // ---- O += P V  (fp16 3-pass) ----
        #pragma unroll
        for (int ks = 0; ks < 4; ks++) {
            uint32_t pah[4], pal[4];
            const int cc = 16*ks + 2*lc;
            pah[0] = *(const uint32_t*)&Ph[prow0 + cc];
            pah[1] = *(const uint32_t*)&Ph[prow1 + cc];
            pah[2] = *(const uint32_t*)&Ph[prow0 + cc + 8];
            pah[3] = *(const uint32_t*)&Ph[prow1 + cc + 8];
            pal[0] = *(const uint32_t*)&Pl[prow0 + cc];
            pal[1] = *(const uint32_t*)&Pl[prow1 + cc];
            pal[2] = *(const uint32_t*)&Pl[prow0 + cc + 8];
            pal[3] = *(const uint32_t*)&Pl[prow1 + cc + 8];
            #pragma unroll
            for (int dt = 0; dt < 8; dt++) {
                const int vr = (dt*8 + lr)*72 + cc;
                uint32_t vh0 = *(const uint32_t*)&Vh[vr];
                uint32_t vh1 = *(const uint32_t*)&Vh[vr + 8];
                uint32_t vl0 = *(const uint32_t*)&Vl[vr];
                uint32_t vl1 = *(const uint32_t*)&Vl[vr + 8];
                mma_fp16(o[dt], pah, vh0, vh1);
                mma_fp16(o[dt], pah, vl0, vl1);
                mma_fp16(o[dt], pal, vh0, vh1);
            }
        }
        __syncthreads();   // all reads of this stage done before reload
    }

    // ---- finalize ----
    l0 += __shfl_xor_sync(0xffffffffu, l0, 1);
    l0 += __shfl_xor_sync(0xffffffffu, l0, 2);
    l1 += __shfl_xor_sync(0xffffffffu, l1, 1);
    l1 += __shfl_xor_sync(0xffffffffu, l1, 2);
    const float inv0 = 1.f / l0;
    const float inv1 = 1.f / l1;

    float* out0 = out + ((size_t)(b*T_ + rg0))*C_ + h*D_;
    float* out1 = out + ((size_t)(b*T_ + rg1))*C_ + h*D_;
    #pragma unroll
    for (int dt = 0; dt < 8; dt++) {
        *(float2*)(out0 + dt*8 + 2*lc) = make_float2(o[dt][0]*inv0, o[dt][1]*inv0);
        *(float2*)(out1 + dt*8 + 2*lc) = make_float2(o[dt][2]*inv1, o[dt][3]*inv1);
    }
}

// ----------------------------------------------------------------------------
extern "C" void kernel_launch(void* const* d_in, const int* in_sizes, int n_in,
                              void* d_out, int out_size)
{
    const float* x_norm = (const float*)d_in[0];
    const float* xt_cur = (const float*)d_in[1];
    const float* W_attn = (const float*)d_in[2];
    const float* b_attn = (const float*)d_in[3];
    float* out = (float*)d_out;

    cudaFuncSetAttribute(gemm_qk_kernel,
                         cudaFuncAttributeMaxDynamicSharedMemorySize, GEMM_SMEM_BYTES);
    cudaFuncSetAttribute(attn_kernel,
                         cudaFuncAttributeMaxDynamicSharedMemorySize, ATTN_SMEM_BYTES);

    prep_x_kernel<<<(M_GEMM*K_GEMM/2)/256, 256>>>(x_norm);
    prep_w_kernel<<<dim3(N_GEMM/32, K_GEMM/32), dim3(32, 8)>>>(W_attn);
    prep_v_kernel<<<dim3(T_/32, D_/32, BH_), dim3(32, 8)>>>(xt_cur);

    dim3 g1(N_GEMM/128, M_GEMM/128);   // (16, 32)
    gemm_qk_kernel<<<g1, 256, GEMM_SMEM_BYTES>>>(b_attn);

    dim3 g2(T_/128, B_*H_);            // (16, 32)
    attn_kernel<<<g2, 256, ATTN_SMEM_BYTES>>>(out);
}

// round 6
// speedup vs baseline: 3.6173x; 1.1452x over previous
#include <cuda_runtime.h>
#include <cuda_fp16.h>
#include <cstdint>

// ============================================================================
// FactoredCausalSelfAttention  (B=2, T=2048, C=1024, H=16, D=64)
// Round 6: round-4 structure (all-fp16 split-precision mma.sync) with
//          ldmatrix.x4 fragment loads in GEMM + attention hot loops.
//          (tcgen05 unavailable: harness PTX target is sm_103 w/o 'a'.)
// ============================================================================

#define B_   2
#define T_   2048
#define C_   1024
#define H_   16
#define D_   64
#define BH_  (B_*H_)
#define M_GEMM (B_*T_)      // 4096
#define N_GEMM (2*C_)       // 2048
#define K_GEMM (C_)         // 1024

// ---- device scratch ----
__device__ __align__(16) __half g_Xh [(size_t)M_GEMM*K_GEMM];
__device__ __align__(16) __half g_Xl [(size_t)M_GEMM*K_GEMM];
__device__ __align__(16) __half g_Whi[(size_t)N_GEMM*K_GEMM];  // [n][k]
__device__ __align__(16) __half g_Wlo[(size_t)N_GEMM*K_GEMM];  // [n][k]
__device__ __align__(16) __half g_qh [(size_t)BH_*T_*D_];      // [bh][t][d]
__device__ __align__(16) __half g_ql [(size_t)BH_*T_*D_];
__device__ __align__(16) __half g_kh [(size_t)BH_*T_*D_];
__device__ __align__(16) __half g_kl [(size_t)BH_*T_*D_];
__device__ __align__(16) __half g_vh [(size_t)BH_*D_*T_];      // [bh][d][t]
__device__ __align__(16) __half g_vl [(size_t)BH_*D_*T_];

// ---------------------------------------------------------------- helpers ---
__device__ __forceinline__ void mma_fp16(float c[4], const uint32_t a[4],
                                         uint32_t b0, uint32_t b1)
{
    asm volatile(
        "mma.sync.aligned.m16n8k16.row.col.f32.f16.f16.f32 "
        "{%0,%1,%2,%3}, {%4,%5,%6,%7}, {%8,%9}, {%0,%1,%2,%3};\n"
        : "+f"(c[0]), "+f"(c[1]), "+f"(c[2]), "+f"(c[3])
        : "r"(a[0]), "r"(a[1]), "r"(a[2]), "r"(a[3]), "r"(b0), "r"(b1));
}

__device__ __forceinline__ void ldsm_x4(uint32_t r[4], uint32_t addr)
{
    asm volatile("ldmatrix.sync.aligned.m8n8.x4.shared.b16 {%0,%1,%2,%3}, [%4];"
                 : "=r"(r[0]), "=r"(r[1]), "=r"(r[2]), "=r"(r[3]) : "r"(addr));
}

__device__ __forceinline__ float ex2f(float x) {
    float y;
    asm("ex2.approx.f32 %0, %1;" : "=f"(y) : "f"(x));
    return y;
}

__device__ __forceinline__ void cp_async16(uint32_t smem_addr, const void* gptr) {
    asm volatile("cp.async.ca.shared.global [%0], [%1], 16;\n"
                 :: "r"(smem_addr), "l"(gptr));
}
__device__ __forceinline__ void cp_async_commit() {
    asm volatile("cp.async.commit_group;\n");
}
template<int N>
__device__ __forceinline__ void cp_async_wait() {
    asm volatile("cp.async.wait_group %0;\n" :: "n"(N));
}

// ----------------------------------------------------------------------------
// prep kernels (unchanged)
// ----------------------------------------------------------------------------
__global__ __launch_bounds__(256) void prep_x_kernel(const float* __restrict__ X)
{
    int i = blockIdx.x * 256 + threadIdx.x;
    float2 v = ((const float2*)X)[i];
    __half h0 = __float2half_rn(v.x);
    __half h1 = __float2half_rn(v.y);
    ((__half2*)g_Xh)[i] = __halves2half2(h0, h1);
    ((__half2*)g_Xl)[i] = __halves2half2(__float2half_rn(v.x - __half2float(h0)),
                                         __float2half_rn(v.y - __half2float(h1)));
}

__global__ __launch_bounds__(256) void prep_w_kernel(const float* __restrict__ W)
{
    __shared__ float t[32][33];
    const int bn = blockIdx.x, bk = blockIdx.y;
    const int tx = threadIdx.x, ty = threadIdx.y;
    #pragma unroll
    for (int j = 0; j < 4; j++)
        t[ty + 8*j][tx] = W[(size_t)(bk*32 + ty + 8*j) * N_GEMM + bn*32 + tx];
    __syncthreads();
    #pragma unroll
    for (int j = 0; j < 4; j++) {
        const int n = bn*32 + ty + 8*j;
        const int k = bk*32 + tx;
        float v = t[tx][ty + 8*j];
        __half h = __float2half_rn(v);
        g_Whi[(size_t)n * K_GEMM + k] = h;
        g_Wlo[(size_t)n * K_GEMM + k] = __float2half_rn(v - __half2float(h));
    }
}

__global__ __launch_bounds__(256) void prep_v_kernel(const float* __restrict__ xt)
{
    __shared__ float t[32][33];
    const int bh = blockIdx.z;
    const int b = bh >> 4, h = bh & 15;
    const int tt = blockIdx.x * 32;
    const int dd = blockIdx.y * 32;
    const int tx = threadIdx.x, ty = threadIdx.y;
    #pragma unroll
    for (int j = 0; j < 4; j++)
        t[ty + 8*j][tx] = xt[(size_t)(b*T_ + tt + ty + 8*j) * C_ + h*D_ + dd + tx];
    __syncthreads();
    #pragma unroll
    for (int j = 0; j < 4; j++) {
        const int d = dd + ty + 8*j;
        float v = t[tx][ty + 8*j];
        __half hh = __float2half_rn(v);
        const size_t o = ((size_t)bh*D_ + d) * T_ + tt + tx;
        g_vh[o] = hh;
        g_vl[o] = __float2half_rn(v - __half2float(hh));
    }
}

// ----------------------------------------------------------------------------
// GEMM (fp16 3-pass): qk = X @ W + bias -> split-scatter q/k hi/lo fp16
// CTA 128x128, BK=32, 8 warps (4m x 2n), 2-stage cp.async, ldmatrix frags.
// ----------------------------------------------------------------------------
#define G_ARR (128*40)
#define G_STAGE (4*G_ARR)
#define GEMM_SMEM_BYTES (2*G_STAGE*2)   // 81920

__global__ __launch_bounds__(256, 2) void gemm_qk_kernel(const float* __restrict__ bias)
{
    extern __shared__ __half gsm[];
    const uint32_t smb = (uint32_t)__cvta_generic_to_shared(gsm);

    const int bx = blockIdx.x;
    const int by = blockIdx.y;
    const int tid = threadIdx.x;
    const int warp = tid >> 5;
    const int lane = tid & 31;
    const int lr = lane >> 2;
    const int lc = lane & 3;
    const int wm = warp >> 1;
    const int wn = warp & 1;

    // ldmatrix row/col patterns (in halves)
    const int aRow = (lane & 15);            // + tile base row
    const int aCol = (lane >> 4) * 8;        // + 16*ks
    const int bRow = ((lane >> 4) << 3) + (lane & 7);
    const int bCol = ((lane >> 3) & 1) * 8;

    float c[2][8][4];
    #pragma unroll
    for (int mt = 0; mt < 2; mt++)
        #pragma unroll
        for (int nt = 0; nt < 8; nt++)
            #pragma unroll
            for (int j = 0; j < 4; j++) c[mt][nt][j] = 0.f;

    auto issue_stage = [&](int stage, int k0) {
        const uint32_t st = smb + (uint32_t)(stage * G_STAGE) * 2;
        #pragma unroll
        for (int i = 0; i < 8; i++) {
            int idx = tid + i * 256;
            int sec = idx >> 9;
            int sub = idx & 511;
            int r   = sub >> 2;
            int c8  = (sub & 3) * 8;
            const __half* src;
            if      (sec == 0) src = g_Xh  + (size_t)(by*128 + r) * K_GEMM + k0 + c8;
            else if (sec == 1) src = g_Xl  + (size_t)(by*128 + r) * K_GEMM + k0 + c8;
            else if (sec == 2) src = g_Whi + (size_t)(bx*128 + r) * K_GEMM + k0 + c8;
            else               src = g_Wlo + (size_t)(bx*128 + r) * K_GEMM + k0 + c8;
            cp_async16(st + (uint32_t)(sec * G_ARR + r * 40 + c8) * 2, src);
        }
        cp_async_commit();
    };

    issue_stage(0, 0);

    const int NIT = K_GEMM / 32;
    for (int it = 0; it < NIT; it++) {
        if (it + 1 < NIT) {
            issue_stage((it + 1) & 1, (it + 1) * 32);
            cp_async_wait<1>();
        } else {
            cp_async_wait<0>();
        }
        __syncthreads();

        const uint32_t Ah = smb + (uint32_t)((it & 1) * G_STAGE) * 2;
        const uint32_t Al = Ah + G_ARR * 2;
        const uint32_t Bh = Ah + 2 * G_ARR * 2;
        const uint32_t Bl = Ah + 3 * G_ARR * 2;

        #pragma unroll
        for (int ks = 0; ks < 2; ks++) {
            uint32_t ah[2][4], al[2][4];
            #pragma unroll
            for (int mt = 0; mt < 2; mt++) {
                const uint32_t ao =
                    (uint32_t)(((wm*32 + mt*16 + aRow) * 40) + 16*ks + aCol) * 2;
                ldsm_x4(ah[mt], Ah + ao);
                ldsm_x4(al[mt], Al + ao);
            }
            #pragma unroll
            for (int ntp = 0; ntp < 4; ntp++) {      // nt pairs
                const uint32_t bo =
                    (uint32_t)(((wn*64 + ntp*16 + bRow) * 40) + 16*ks + bCol) * 2;
                uint32_t bh4[4], bl4[4];
                ldsm_x4(bh4, Bh + bo);
                ldsm_x4(bl4, Bl + bo);
                #pragma unroll
                for (int half = 0; half < 2; half++) {
                    const int nt = 2*ntp + half;
                    const uint32_t b0h = bh4[2*half], b1h = bh4[2*half + 1];
                    const uint32_t b0l = bl4[2*half], b1l = bl4[2*half + 1];
                    #pragma unroll
                    for (int mt = 0; mt < 2; mt++) {
                        mma_fp16(c[mt][nt], ah[mt], b0h, b1h);
                        mma_fp16(c[mt][nt], ah[mt], b0l, b1l);
                        mma_fp16(c[mt][nt], al[mt], b0h, b1h);
                    }
                }
            }
        }
        __syncthreads();
    }

    #pragma unroll
    for (int mt = 0; mt < 2; mt++) {
        #pragma unroll
        for (int rr = 0; rr < 2; rr++) {
            const int m = by*128 + wm*32 + mt*16 + rr*8 + lr;
            const int b = m >> 11;
            const int t = m & (T_ - 1);
            #pragma unroll
            for (int nt = 0; nt < 8; nt++) {
                const int n0 = bx*128 + wn*64 + nt*8 + 2*lc;
                const float v0 = c[mt][nt][rr*2 + 0] + bias[n0];
                const float v1 = c[mt][nt][rr*2 + 1] + bias[n0 + 1];
                __half h0 = __float2half_rn(v0);
                __half h1 = __float2half_rn(v1);
                __half l0 = __float2half_rn(v0 - __half2float(h0));
                __half l1 = __float2half_rn(v1 - __half2float(h1));
                if (n0 < C_) {
                    const int hh = n0 >> 6, d = n0 & 63;
                    const size_t o = (((size_t)(b*H_ + hh)) * T_ + t) * D_ + d;
                    *(__half2*)&g_qh[o] = __halves2half2(h0, h1);
                    *(__half2*)&g_ql[o] = __halves2half2(l0, l1);
                } else {
                    const int n2 = n0 - C_;
                    const int hh = n2 >> 6, d = n2 & 63;
                    const size_t o = (((size_t)(b*H_ + hh)) * T_ + t) * D_ + d;
                    *(__half2*)&g_kh[o] = __halves2half2(h0, h1);
                    *(__half2*)&g_kl[o] = __halves2half2(l0, l1);
                }
            }
        }
    }
}

// ----------------------------------------------------------------------------
// Flash attention: fp16 3-pass QK^T and PV, ldmatrix frags, cp.async KV pipe.
// smem: stage s @ s*36864: Khi[64][72] Klo Vh Vl (half)
//       P/Q @ 73728: Ph[128][72], Pl[128][72]
// ----------------------------------------------------------------------------
#define A_STAGE 36864
#define A_PQ    73728
#define ATTN_SMEM_BYTES 110592

__global__ __launch_bounds__(256) void attn_kernel(float* __restrict__ out)
{
    extern __shared__ char smraw[];
    const uint32_t sm_base = (uint32_t)__cvta_generic_to_shared(smraw);
    __half* Ph  = (__half*)(smraw + A_PQ);
    __half* Pl  = Ph + 128*72;
    const uint32_t PhU = sm_base + A_PQ;
    const uint32_t PlU = PhU + 128*72*2;

    const int bh = blockIdx.y;
    const int b  = bh >> 4;
    const int h  = bh & 15;
    const int tid  = threadIdx.x;
    const int warp = tid >> 5;
    const int lane = tid & 31;
    const int lr = lane >> 2;
    const int lc = lane & 3;
    const int qt = gridDim.x - 1 - blockIdx.x;
    const int t0 = qt * 128;

    // ldmatrix patterns (halves)
    const int aRow = (lane & 15);
    const int aCol = (lane >> 4) * 8;
    const int bRow = ((lane >> 4) << 3) + (lane & 7);
    const int bCol = ((lane >> 3) & 1) * 8;

    // ---- stage Q hi/lo into P region, build register A fragments ----
    {
        __half* Qhs = Ph;
        __half* Qls = Pl;
        #pragma unroll
        for (int i = 0; i < 4; i++) {
            int idx = tid + i * 256;
            int r = idx >> 3, c8 = (idx & 7) * 8;
            *(float4*)&Qhs[r*72 + c8] =
                *(const float4*)(g_qh + ((size_t)bh*T_ + t0 + r)*D_ + c8);
            *(float4*)&Qls[r*72 + c8] =
                *(const float4*)(g_ql + ((size_t)bh*T_ + t0 + r)*D_ + c8);
        }
    }
    __syncthreads();

    uint32_t qfh[4][4], qfl[4][4];
    #pragma unroll
    for (int ks = 0; ks < 4; ks++) {
        const uint32_t qo = (uint32_t)(((warp*16 + aRow) * 72) + 16*ks + aCol) * 2;
        ldsm_x4(qfh[ks], PhU + qo);
        ldsm_x4(qfl[ks], PlU + qo);
    }
    __syncthreads();

    float o[8][4];
    #pragma unroll
    for (int dt = 0; dt < 8; dt++)
        #pragma unroll
        for (int j = 0; j < 4; j++) o[dt][j] = 0.f;

    float m0 = -1e30f, m1 = -1e30f;
    float l0 = 0.f, l1 = 0.f;
    const float C2 = 0.125f * 1.44269504089f;

    const int rg0 = t0 + warp*16 + lr;
    const int rg1 = rg0 + 8;
    const int prow0 = (warp*16 + lr) * 72;
    const int prow1 = prow0 + 8*72;

    auto issue_tile = [&](int stage, int j0) {
        const uint32_t st = sm_base + (uint32_t)stage * A_STAGE;
        #pragma unroll
        for (int i = 0; i < 8; i++) {
            int idx = tid + i * 256;
            int sec = idx >> 9;
            int sub = idx & 511;
            int r   = sub >> 3;
            int c8  = (sub & 7) * 8;
            const __half* src;
            if      (sec == 0) src = g_kh + ((size_t)bh*T_ + j0 + r)*D_ + c8;
            else if (sec == 1) src = g_kl + ((size_t)bh*T_ + j0 + r)*D_ + c8;
            else if (sec == 2) src = g_vh + ((size_t)bh*D_ + r)*T_ + j0 + c8;
            else               src = g_vl + ((size_t)bh*D_ + r)*T_ + j0 + c8;
            cp_async16(st + (uint32_t)(sec * 9216) + (uint32_t)(r*72 + c8)*2, src);
        }
        cp_async_commit();
    };

    const int ntiles = 2*qt + 2;
    issue_tile(0, 0);

    for (int it = 0; it < ntiles; it++) {
        const int j0 = it * 64;
        if (it + 1 < ntiles) {
            issue_tile((it + 1) & 1, (it + 1) * 64);
            cp_async_wait<1>();
        } else {
            cp_async_wait<0>();
        }
        __syncthreads();

        const uint32_t KhiU = sm_base + (uint32_t)((it & 1) * A_STAGE);
        const uint32_t KloU = KhiU + 9216;
        const uint32_t VhU  = KhiU + 2*9216;
        const uint32_t VlU  = KhiU + 3*9216;

        // ---- S = Q K^T  (fp16 3-pass, ldmatrix B-frags) ----
        float s[8][4];
        #pragma unroll
        for (int nt = 0; nt < 8; nt++)
            #pragma unroll
            for (int j = 0; j < 4; j++) s[nt][j] = 0.f;

        #pragma unroll
        for (int ks = 0; ks < 4; ks++) {
            #pragma unroll
            for (int ntp = 0; ntp < 4; ntp++) {
                const uint32_t ko =
                    (uint32_t)(((ntp*16 + bRow) * 72) + 16*ks + bCol) * 2;
                uint32_t kh4[4], kl4[4];
                ldsm_x4(kh4, KhiU + ko);
                ldsm_x4(kl4, KloU + ko);
                #pragma unroll
                for (int half = 0; half < 2; half++) {
                    const int nt = 2*ntp + half;
                    mma_fp16(s[nt], qfh[ks], kh4[2*half], kh4[2*half+1]);
                    mma_fp16(s[nt], qfh[ks], kl4[2*half], kl4[2*half+1]);
                    mma_fp16(s[nt], qfl[ks], kh4[2*half], kh4[2*half+1]);
                }
            }
        }

        // ---- causal mask ----
        if (j0 + 63 > t0) {
            #pragma unroll
            for (int nt = 0; nt < 8; nt++) {
                int cg = j0 + nt*8 + 2*lc;
                if (cg     > rg0) s[nt][0] = -1e30f;
                if (cg + 1 > rg0) s[nt][1] = -1e30f;
                if (cg     > rg1) s[nt][2] = -1e30f;
                if (cg + 1 > rg1) s[nt][3] = -1e30f;
            }
        }

        // ---- online softmax ----
        float t0m = -1e30f, t1m = -1e30f;
        #pragma unroll
        for (int nt = 0; nt < 8; nt++) {
            t0m = fmaxf(t0m, fmaxf(s[nt][0], s[nt][1]));
            t1m = fmaxf(t1m, fmaxf(s[nt][2], s[nt][3]));
        }
        t0m = fmaxf(t0m, __shfl_xor_sync(0xffffffffu, t0m, 1));
        t0m = fmaxf(t0m, __shfl_xor_sync(0xffffffffu, t0m, 2));
        t1m = fmaxf(t1m, __shfl_xor_sync(0xffffffffu, t1m, 1));
        t1m = fmaxf(t1m, __shfl_xor_sync(0xffffffffu, t1m, 2));

        const float mn0 = fmaxf(m0, t0m);
        const float mn1 = fmaxf(m1, t1m);
        const float a0 = ex2f((m0 - mn0) * C2);
        const float a1 = ex2f((m1 - mn1) * C2);
        m0 = mn0; m1 = mn1;
        l0 *= a0; l1 *= a1;
        #pragma unroll
        for (int dt = 0; dt < 8; dt++) {
            o[dt][0] *= a0; o[dt][1] *= a0;
            o[dt][2] *= a1; o[dt][3] *= a1;
        }

        // ---- p split into fp16 hi/lo; l in fp32 ----
        #pragma unroll
        for (int nt = 0; nt < 8; nt++) {
            float p0 = ex2f((s[nt][0] - m0) * C2);
            float p1 = ex2f((s[nt][1] - m0) * C2);
            float p2 = ex2f((s[nt][2] - m1) * C2);
            float p3 = ex2f((s[nt][3] - m1) * C2);
            l0 += p0 + p1;
            l1 += p2 + p3;
            __half h0 = __float2half_rn(p0), h1 = __float2half_rn(p1);
            __half h2 = __float2half_rn(p2), h3 = __float2half_rn(p3);
            *(__half2*)&Ph[prow0 + nt*8 + 2*lc] = __halves2half2(h0, h1);
            *(__half2*)&Ph[prow1 + nt*8 + 2*lc] = __halves2half2(h2, h3);
            *(__half2*)&Pl[prow0 + nt*8 + 2*lc] =
                __halves2half2(__float2half_rn(p0 - __half2float(h0)),
                               __float2half_rn(p1 - __half2float(h1)));
            *(__half2*)&Pl[prow1 + nt*8 + 2*lc] =
                __halves2half2(__float2half_rn(p2 - __half2float(h2)),
                               __float2half_rn(p3 - __half2float(h3)));
        }
        __syncwarp();   // P rows are per-warp private

        // ---- O += P V  (fp16 3-pass, ldmatrix A+B frags) ----
        #pragma unroll
        for (int ks = 0; ks < 4; ks++) {
            uint32_t pah[4], pal[4];
            const uint32_t po =
                (uint32_t)(((warp*16 + aRow) * 72) + 16*ks + aCol) * 2;
            ldsm_x4(pah, PhU + po);
            ldsm_x4(pal, PlU + po);
            #pragma unroll
            for (int dtp = 0; dtp < 4; dtp++) {
                const uint32_t vo =
                    (uint32_t)(((dtp*16 + bRow) * 72) + 16*ks + bCol) * 2;
                uint32_t vh4[4], vl4[4];
                ldsm_x4(vh4, VhU + vo);
                ldsm_x4(vl4, VlU + vo);
                #pragma unroll
                for (int half = 0; half < 2; half++) {
                    const int dt = 2*dtp + half;
                    mma_fp16(o[dt], pah, vh4[2*half], vh4[2*half+1]);
                    mma_fp16(o[dt], pah, vl4[2*half], vl4[2*half+1]);
                    mma_fp16(o[dt], pal, vh4[2*half], vh4[2*half+1]);
                }
            }
        }
        __syncthreads();
    }

    // ---- finalize ----
    l0 += __shfl_xor_sync(0xffffffffu, l0, 1);
    l0 += __shfl_xor_sync(0xffffffffu, l0, 2);
    l1 += __shfl_xor_sync(0xffffffffu, l1, 1);
    l1 += __shfl_xor_sync(0xffffffffu, l1, 2);
    const float inv0 = 1.f / l0;
    const float inv1 = 1.f / l1;

    float* out0 = out + ((size_t)(b*T_ + rg0))*C_ + h*D_;
    float* out1 = out + ((size_t)(b*T_ + rg1))*C_ + h*D_;
    #pragma unroll
    for (int dt = 0; dt < 8; dt++) {
        *(float2*)(out0 + dt*8 + 2*lc) = make_float2(o[dt][0]*inv0, o[dt][1]*inv0);
        *(float2*)(out1 + dt*8 + 2*lc) = make_float2(o[dt][2]*inv1, o[dt][3]*inv1);
    }
}

// ----------------------------------------------------------------------------
extern "C" void kernel_launch(void* const* d_in, const int* in_sizes, int n_in,
                              void* d_out, int out_size)
{
    const float* x_norm = (const float*)d_in[0];
    const float* xt_cur = (const float*)d_in[1];
    const float* W_attn = (const float*)d_in[2];
    const float* b_attn = (const float*)d_in[3];
    float* out = (float*)d_out;

    cudaFuncSetAttribute(gemm_qk_kernel,
                         cudaFuncAttributeMaxDynamicSharedMemorySize, GEMM_SMEM_BYTES);
    cudaFuncSetAttribute(attn_kernel,
                         cudaFuncAttributeMaxDynamicSharedMemorySize, ATTN_SMEM_BYTES);

    prep_x_kernel<<<(M_GEMM*K_GEMM/2)/256, 256>>>(x_norm);
    prep_w_kernel<<<dim3(N_GEMM/32, K_GEMM/32), dim3(32, 8)>>>(W_attn);
    prep_v_kernel<<<dim3(T_/32, D_/32, BH_), dim3(32, 8)>>>(xt_cur);

    dim3 g1(N_GEMM/128, M_GEMM/128);   // (16, 32)
    gemm_qk_kernel<<<g1, 256, GEMM_SMEM_BYTES>>>(b_attn);

    dim3 g2(T_/128, B_*H_);            // (16, 32)
    attn_kernel<<<g2, 256, ATTN_SMEM_BYTES>>>(out);
}

// round 7
// speedup vs baseline: 3.6392x; 1.0061x over previous
#include <cuda_runtime.h>
#include <cuda_fp16.h>
#include <cstdint>

// ============================================================================
// FactoredCausalSelfAttention  (B=2, T=2048, C=1024, H=16, D=64)
// Round 7: round-6 structure + accumulator-dependency-breaking mma order
//          (pass-outermost issue; revisit distance 4/8 instead of 1).
// ============================================================================

#define B_   2
#define T_   2048
#define C_   1024
#define H_   16
#define D_   64
#define BH_  (B_*H_)
#define M_GEMM (B_*T_)      // 4096
#define N_GEMM (2*C_)       // 2048
#define K_GEMM (C_)         // 1024

// ---- device scratch ----
__device__ __align__(16) __half g_Xh [(size_t)M_GEMM*K_GEMM];
__device__ __align__(16) __half g_Xl [(size_t)M_GEMM*K_GEMM];
__device__ __align__(16) __half g_Whi[(size_t)N_GEMM*K_GEMM];  // [n][k]
__device__ __align__(16) __half g_Wlo[(size_t)N_GEMM*K_GEMM];  // [n][k]
__device__ __align__(16) __half g_qh [(size_t)BH_*T_*D_];      // [bh][t][d]
__device__ __align__(16) __half g_ql [(size_t)BH_*T_*D_];
__device__ __align__(16) __half g_kh [(size_t)BH_*T_*D_];
__device__ __align__(16) __half g_kl [(size_t)BH_*T_*D_];
__device__ __align__(16) __half g_vh [(size_t)BH_*D_*T_];      // [bh][d][t]
__device__ __align__(16) __half g_vl [(size_t)BH_*D_*T_];

// ---------------------------------------------------------------- helpers ---
__device__ __forceinline__ void mma_fp16(float c[4], const uint32_t a[4],
                                         uint32_t b0, uint32_t b1)
{
    asm volatile(
        "mma.sync.aligned.m16n8k16.row.col.f32.f16.f16.f32 "
        "{%0,%1,%2,%3}, {%4,%5,%6,%7}, {%8,%9}, {%0,%1,%2,%3};\n"
        : "+f"(c[0]), "+f"(c[1]), "+f"(c[2]), "+f"(c[3])
        : "r"(a[0]), "r"(a[1]), "r"(a[2]), "r"(a[3]), "r"(b0), "r"(b1));
}

__device__ __forceinline__ void ldsm_x4(uint32_t r[4], uint32_t addr)
{
    asm volatile("ldmatrix.sync.aligned.m8n8.x4.shared.b16 {%0,%1,%2,%3}, [%4];"
                 : "=r"(r[0]), "=r"(r[1]), "=r"(r[2]), "=r"(r[3]) : "r"(addr));
}

__device__ __forceinline__ float ex2f(float x) {
    float y;
    asm("ex2.approx.f32 %0, %1;" : "=f"(y) : "f"(x));
    return y;
}

__device__ __forceinline__ void cp_async16(uint32_t smem_addr, const void* gptr) {
    asm volatile("cp.async.ca.shared.global [%0], [%1], 16;\n"
                 :: "r"(smem_addr), "l"(gptr));
}
__device__ __forceinline__ void cp_async_commit() {
    asm volatile("cp.async.commit_group;\n");
}
template<int N>
__device__ __forceinline__ void cp_async_wait() {
    asm volatile("cp.async.wait_group %0;\n" :: "n"(N));
}

// ----------------------------------------------------------------------------
// prep kernels (unchanged)
// ----------------------------------------------------------------------------
__global__ __launch_bounds__(256) void prep_x_kernel(const float* __restrict__ X)
{
    int i = blockIdx.x * 256 + threadIdx.x;
    float2 v = ((const float2*)X)[i];
    __half h0 = __float2half_rn(v.x);
    __half h1 = __float2half_rn(v.y);
    ((__half2*)g_Xh)[i] = __halves2half2(h0, h1);
    ((__half2*)g_Xl)[i] = __halves2half2(__float2half_rn(v.x - __half2float(h0)),
                                         __float2half_rn(v.y - __half2float(h1)));
}

__global__ __launch_bounds__(256) void prep_w_kernel(const float* __restrict__ W)
{
    __shared__ float t[32][33];
    const int bn = blockIdx.x, bk = blockIdx.y;
    const int tx = threadIdx.x, ty = threadIdx.y;
    #pragma unroll
    for (int j = 0; j < 4; j++)
        t[ty + 8*j][tx] = W[(size_t)(bk*32 + ty + 8*j) * N_GEMM + bn*32 + tx];
    __syncthreads();
    #pragma unroll
    for (int j = 0; j < 4; j++) {
        const int n = bn*32 + ty + 8*j;
        const int k = bk*32 + tx;
        float v = t[tx][ty + 8*j];
        __half h = __float2half_rn(v);
        g_Whi[(size_t)n * K_GEMM + k] = h;
        g_Wlo[(size_t)n * K_GEMM + k] = __float2half_rn(v - __half2float(h));
    }
}

__global__ __launch_bounds__(256) void prep_v_kernel(const float* __restrict__ xt)
{
    __shared__ float t[32][33];
    const int bh = blockIdx.z;
    const int b = bh >> 4, h = bh & 15;
    const int tt = blockIdx.x * 32;
    const int dd = blockIdx.y * 32;
    const int tx = threadIdx.x, ty = threadIdx.y;
    #pragma unroll
    for (int j = 0; j < 4; j++)
        t[ty + 8*j][tx] = xt[(size_t)(b*T_ + tt + ty + 8*j) * C_ + h*D_ + dd + tx];
    __syncthreads();
    #pragma unroll
    for (int j = 0; j < 4; j++) {
        const int d = dd + ty + 8*j;
        float v = t[tx][ty + 8*j];
        __half hh = __float2half_rn(v);
        const size_t o = ((size_t)bh*D_ + d) * T_ + tt + tx;
        g_vh[o] = hh;
        g_vl[o] = __float2half_rn(v - __half2float(hh));
    }
}

// ----------------------------------------------------------------------------
// GEMM (fp16 3-pass): qk = X @ W + bias -> split-scatter q/k hi/lo fp16
// CTA 128x128, BK=32, 8 warps (4m x 2n), 2-stage cp.async, ldmatrix frags.
// mma issue: pass-outermost per ntp (accumulator revisit distance 4).
// ----------------------------------------------------------------------------
#define G_ARR (128*40)
#define G_STAGE (4*G_ARR)
#define GEMM_SMEM_BYTES (2*G_STAGE*2)   // 81920

__global__ __launch_bounds__(256, 2) void gemm_qk_kernel(const float* __restrict__ bias)
{
    extern __shared__ __half gsm[];
    const uint32_t smb = (uint32_t)__cvta_generic_to_shared(gsm);

    const int bx = blockIdx.x;
    const int by = blockIdx.y;
    const int tid = threadIdx.x;
    const int warp = tid >> 5;
    const int lane = tid & 31;
    const int lr = lane >> 2;
    const int lc = lane & 3;
    const int wm = warp >> 1;
    const int wn = warp & 1;

    const int aRow = (lane & 15);
    const int aCol = (lane >> 4) * 8;
    const int bRow = ((lane >> 4) << 3) + (lane & 7);
    const int bCol = ((lane >> 3) & 1) * 8;

    float c[2][8][4];
    #pragma unroll
    for (int mt = 0; mt < 2; mt++)
        #pragma unroll
        for (int nt = 0; nt < 8; nt++)
            #pragma unroll
            for (int j = 0; j < 4; j++) c[mt][nt][j] = 0.f;

    auto issue_stage = [&](int stage, int k0) {
        const uint32_t st = smb + (uint32_t)(stage * G_STAGE) * 2;
        #pragma unroll
        for (int i = 0; i < 8; i++) {
            int idx = tid + i * 256;
            int sec = idx >> 9;
            int sub = idx & 511;
            int r   = sub >> 2;
            int c8  = (sub & 3) * 8;
            const __half* src;
            if      (sec == 0) src = g_Xh  + (size_t)(by*128 + r) * K_GEMM + k0 + c8;
            else if (sec == 1) src = g_Xl  + (size_t)(by*128 + r) * K_GEMM + k0 + c8;
            else if (sec == 2) src = g_Whi + (size_t)(bx*128 + r) * K_GEMM + k0 + c8;
            else               src = g_Wlo + (size_t)(bx*128 + r) * K_GEMM + k0 + c8;
            cp_async16(st + (uint32_t)(sec * G_ARR + r * 40 + c8) * 2, src);
        }
        cp_async_commit();
    };

    issue_stage(0, 0);

    const int NIT = K_GEMM / 32;
    for (int it = 0; it < NIT; it++) {
        if (it + 1 < NIT) {
            issue_stage((it + 1) & 1, (it + 1) * 32);
            cp_async_wait<1>();
        } else {
            cp_async_wait<0>();
        }
        __syncthreads();

        const uint32_t Ah = smb + (uint32_t)((it & 1) * G_STAGE) * 2;
        const uint32_t Al = Ah + G_ARR * 2;
        const uint32_t Bh = Ah + 2 * G_ARR * 2;
        const uint32_t Bl = Ah + 3 * G_ARR * 2;

        #pragma unroll
        for (int ks = 0; ks < 2; ks++) {
            uint32_t ah[2][4], al[2][4];
            #pragma unroll
            for (int mt = 0; mt < 2; mt++) {
                const uint32_t ao =
                    (uint32_t)(((wm*32 + mt*16 + aRow) * 40) + 16*ks + aCol) * 2;
                ldsm_x4(ah[mt], Ah + ao);
                ldsm_x4(al[mt], Al + ao);
            }
            #pragma unroll
            for (int ntp = 0; ntp < 4; ntp++) {
                const uint32_t bo =
                    (uint32_t)(((wn*64 + ntp*16 + bRow) * 40) + 16*ks + bCol) * 2;
                uint32_t bh4[4], bl4[4];
                ldsm_x4(bh4, Bh + bo);
                ldsm_x4(bl4, Bl + bo);
                // pass-outermost: accumulator revisit distance = 4
                #pragma unroll
                for (int half = 0; half < 2; half++)
                    #pragma unroll
                    for (int mt = 0; mt < 2; mt++)
                        mma_fp16(c[mt][2*ntp+half], ah[mt], bh4[2*half], bh4[2*half+1]);
                #pragma unroll
                for (int half = 0; half < 2; half++)
                    #pragma unroll
                    for (int mt = 0; mt < 2; mt++)
                        mma_fp16(c[mt][2*ntp+half], ah[mt], bl4[2*half], bl4[2*half+1]);
                #pragma unroll
                for (int half = 0; half < 2; half++)
                    #pragma unroll
                    for (int mt = 0; mt < 2; mt++)
                        mma_fp16(c[mt][2*ntp+half], al[mt], bh4[2*half], bh4[2*half+1]);
            }
        }
        __syncthreads();
    }

    #pragma unroll
    for (int mt = 0; mt < 2; mt++) {
        #pragma unroll
        for (int rr = 0; rr < 2; rr++) {
            const int m = by*128 + wm*32 + mt*16 + rr*8 + lr;
            const int b = m >> 11;
            const int t = m & (T_ - 1);
            #pragma unroll
            for (int nt = 0; nt < 8; nt++) {
                const int n0 = bx*128 + wn*64 + nt*8 + 2*lc;
                const float v0 = c[mt][nt][rr*2 + 0] + bias[n0];
                const float v1 = c[mt][nt][rr*2 + 1] + bias[n0 + 1];
                __half h0 = __float2half_rn(v0);
                __half h1 = __float2half_rn(v1);
                __half l0 = __float2half_rn(v0 - __half2float(h0));
                __half l1 = __float2half_rn(v1 - __half2float(h1));
                if (n0 < C_) {
                    const int hh = n0 >> 6, d = n0 & 63;
                    const size_t o = (((size_t)(b*H_ + hh)) * T_ + t) * D_ + d;
                    *(__half2*)&g_qh[o] = __halves2half2(h0, h1);
                    *(__half2*)&g_ql[o] = __halves2half2(l0, l1);
                } else {
                    const int n2 = n0 - C_;
                    const int hh = n2 >> 6, d = n2 & 63;
                    const size_t o = (((size_t)(b*H_ + hh)) * T_ + t) * D_ + d;
                    *(__half2*)&g_kh[o] = __halves2half2(h0, h1);
                    *(__half2*)&g_kl[o] = __halves2half2(l0, l1);
                }
            }
        }
    }
}

// ----------------------------------------------------------------------------
// Flash attention: fp16 3-pass QK^T and PV, ldmatrix frags, cp.async KV pipe.
// mma issue: all fragments for a ks hoisted, pass-outermost (distance 8).
// ----------------------------------------------------------------------------
#define A_STAGE 36864
#define A_PQ    73728
#define ATTN_SMEM_BYTES 110592

__global__ __launch_bounds__(256) void attn_kernel(float* __restrict__ out)
{
    extern __shared__ char smraw[];
    const uint32_t sm_base = (uint32_t)__cvta_generic_to_shared(smraw);
    __half* Ph  = (__half*)(smraw + A_PQ);
    __half* Pl  = Ph + 128*72;
    const uint32_t PhU = sm_base + A_PQ;
    const uint32_t PlU = PhU + 128*72*2;

    const int bh = blockIdx.y;
    const int b  = bh >> 4;
    const int h  = bh & 15;
    const int tid  = threadIdx.x;
    const int warp = tid >> 5;
    const int lane = tid & 31;
    const int lr = lane >> 2;
    const int lc = lane & 3;
    const int qt = gridDim.x - 1 - blockIdx.x;
    const int t0 = qt * 128;

    const int aRow = (lane & 15);
    const int aCol = (lane >> 4) * 8;
    const int bRow = ((lane >> 4) << 3) + (lane & 7);
    const int bCol = ((lane >> 3) & 1) * 8;

    {
        __half* Qhs = Ph;
        __half* Qls = Pl;
        #pragma unroll
        for (int i = 0; i < 4; i++) {
            int idx = tid + i * 256;
            int r = idx >> 3, c8 = (idx & 7) * 8;
            *(float4*)&Qhs[r*72 + c8] =
                *(const float4*)(g_qh + ((size_t)bh*T_ + t0 + r)*D_ + c8);
            *(float4*)&Qls[r*72 + c8] =
                *(const float4*)(g_ql + ((size_t)bh*T_ + t0 + r)*D_ + c8);
        }
    }
    __syncthreads();

    uint32_t qfh[4][4], qfl[4][4];
    #pragma unroll
    for (int ks = 0; ks < 4; ks++) {
        const uint32_t qo = (uint32_t)(((warp*16 + aRow) * 72) + 16*ks + aCol) * 2;
        ldsm_x4(qfh[ks], PhU + qo);
        ldsm_x4(qfl[ks], PlU + qo);
    }
    __syncthreads();

    float o[8][4];
    #pragma unroll
    for (int dt = 0; dt < 8; dt++)
        #pragma unroll
        for (int j = 0; j < 4; j++) o[dt][j] = 0.f;

    float m0 = -1e30f, m1 = -1e30f;
    float l0 = 0.f, l1 = 0.f;
    const float C2 = 0.125f * 1.44269504089f;

    const int rg0 = t0 + warp*16 + lr;
    const int rg1 = rg0 + 8;
    const int prow0 = (warp*16 + lr) * 72;
    const int prow1 = prow0 + 8*72;

    auto issue_tile = [&](int stage, int j0) {
        const uint32_t st = sm_base + (uint32_t)stage * A_STAGE;
        #pragma unroll
        for (int i = 0; i < 8; i++) {
            int idx = tid + i * 256;
            int sec = idx >> 9;
            int sub = idx & 511;
            int r   = sub >> 3;
            int c8  = (sub & 7) * 8;
            const __half* src;
            if      (sec == 0) src = g_kh + ((size_t)bh*T_ + j0 + r)*D_ + c8;
            else if (sec == 1) src = g_kl + ((size_t)bh*T_ + j0 + r)*D_ + c8;
            else if (sec == 2) src = g_vh + ((size_t)bh*D_ + r)*T_ + j0 + c8;
            else               src = g_vl + ((size_t)bh*D_ + r)*T_ + j0 + c8;
            cp_async16(st + (uint32_t)(sec * 9216) + (uint32_t)(r*72 + c8)*2, src);
        }
        cp_async_commit();
    };

    const int ntiles = 2*qt + 2;
    issue_tile(0, 0);

    for (int it = 0; it < ntiles; it++) {
        const int j0 = it * 64;
        if (it + 1 < ntiles) {
            issue_tile((it + 1) & 1, (it + 1) * 64);
            cp_async_wait<1>();
        } else {
            cp_async_wait<0>();
        }
        __syncthreads();

        const uint32_t KhiU = sm_base + (uint32_t)((it & 1) * A_STAGE);
        const uint32_t KloU = KhiU + 9216;
        const uint32_t VhU  = KhiU + 2*9216;
        const uint32_t VlU  = KhiU + 3*9216;

        // ---- S = Q K^T  (fp16 3-pass, pass-outermost) ----
        float s[8][4];
        #pragma unroll
        for (int nt = 0; nt < 8; nt++)
            #pragma unroll
            for (int j = 0; j < 4; j++) s[nt][j] = 0.f;

        #pragma unroll
        for (int ks = 0; ks < 4; ks++) {
            uint32_t kh4[4][4], kl4[4][4];
            #pragma unroll
            for (int ntp = 0; ntp < 4; ntp++) {
                const uint32_t ko =
                    (uint32_t)(((ntp*16 + bRow) * 72) + 16*ks + bCol) * 2;
                ldsm_x4(kh4[ntp], KhiU + ko);
                ldsm_x4(kl4[ntp], KloU + ko);
            }
            #pragma unroll
            for (int nt = 0; nt < 8; nt++)
                mma_fp16(s[nt], qfh[ks], kh4[nt>>1][2*(nt&1)], kh4[nt>>1][2*(nt&1)+1]);
            #pragma unroll
            for (int nt = 0; nt < 8; nt++)
                mma_fp16(s[nt], qfh[ks], kl4[nt>>1][2*(nt&1)], kl4[nt>>1][2*(nt&1)+1]);
            #pragma unroll
            for (int nt = 0; nt < 8; nt++)
                mma_fp16(s[nt], qfl[ks], kh4[nt>>1][2*(nt&1)], kh4[nt>>1][2*(nt&1)+1]);
        }

        // ---- causal mask ----
        if (j0 + 63 > t0) {
            #pragma unroll
            for (int nt = 0; nt < 8; nt++) {
                int cg = j0 + nt*8 + 2*lc;
                if (cg     > rg0) s[nt][0] = -1e30f;
                if (cg + 1 > rg0) s[nt][1] = -1e30f;
                if (cg     > rg1) s[nt][2] = -1e30f;
                if (cg + 1 > rg1) s[nt][3] = -1e30f;
            }
        }

        // ---- online softmax ----
        float t0m = -1e30f, t1m = -1e30f;
        #pragma unroll
        for (int nt = 0; nt < 8; nt++) {
            t0m = fmaxf(t0m, fmaxf(s[nt][0], s[nt][1]));
            t1m = fmaxf(t1m, fmaxf(s[nt][2], s[nt][3]));
        }
        t0m = fmaxf(t0m, __shfl_xor_sync(0xffffffffu, t0m, 1));
        t0m = fmaxf(t0m, __shfl_xor_sync(0xffffffffu, t0m, 2));
        t1m = fmaxf(t1m, __shfl_xor_sync(0xffffffffu, t1m, 1));
        t1m = fmaxf(t1m, __shfl_xor_sync(0xffffffffu, t1m, 2));

        const float mn0 = fmaxf(m0, t0m);
        const float mn1 = fmaxf(m1, t1m);
        const float a0 = ex2f((m0 - mn0) * C2);
        const float a1 = ex2f((m1 - mn1) * C2);
        m0 = mn0; m1 = mn1;
        l0 *= a0; l1 *= a1;
        #pragma unroll
        for (int dt = 0; dt < 8; dt++) {
            o[dt][0] *= a0; o[dt][1] *= a0;
            o[dt][2] *= a1; o[dt][3] *= a1;
        }

        // ---- p split into fp16 hi/lo; l in fp32 ----
        #pragma unroll
        for (int nt = 0; nt < 8; nt++) {
            float p0 = ex2f((s[nt][0] - m0) * C2);
            float p1 = ex2f((s[nt][1] - m0) * C2);
            float p2 = ex2f((s[nt][2] - m1) * C2);
            float p3 = ex2f((s[nt][3] - m1) * C2);
            l0 += p0 + p1;
            l1 += p2 + p3;
            __half h0 = __float2half_rn(p0), h1 = __float2half_rn(p1);
            __half h2 = __float2half_rn(p2), h3 = __float2half_rn(p3);
            *(__half2*)&Ph[prow0 + nt*8 + 2*lc] = __halves2half2(h0, h1);
            *(__half2*)&Ph[prow1 + nt*8 + 2*lc] = __halves2half2(h2, h3);
            *(__half2*)&Pl[prow0 + nt*8 + 2*lc] =
                __halves2half2(__float2half_rn(p0 - __half2float(h0)),
                               __float2half_rn(p1 - __half2float(h1)));
            *(__half2*)&Pl[prow1 + nt*8 + 2*lc] =
                __halves2half2(__float2half_rn(p2 - __half2float(h2)),
                               __float2half_rn(p3 - __half2float(h3)));
        }
        __syncwarp();   // P rows are per-warp private

        // ---- O += P V  (fp16 3-pass, pass-outermost) ----
        #pragma unroll
        for (int ks = 0; ks < 4; ks++) {
            uint32_t pah[4], pal[4];
            const uint32_t po =
                (uint32_t)(((warp*16 + aRow) * 72) + 16*ks + aCol) * 2;
            ldsm_x4(pah, PhU + po);
            ldsm_x4(pal, PlU + po);
            uint32_t vh4[4][4], vl4[4][4];
            #pragma unroll
            for (int dtp = 0; dtp < 4; dtp++) {
                const uint32_t vo =
                    (uint32_t)(((dtp*16 + bRow) * 72) + 16*ks + bCol) * 2;
                ldsm_x4(vh4[dtp], VhU + vo);
                ldsm_x4(vl4[dtp], VlU + vo);
            }
            #pragma unroll
            for (int dt = 0; dt < 8; dt++)
                mma_fp16(o[dt], pah, vh4[dt>>1][2*(dt&1)], vh4[dt>>1][2*(dt&1)+1]);
            #pragma unroll
            for (int dt = 0; dt < 8; dt++)
                mma_fp16(o[dt], pah, vl4[dt>>1][2*(dt&1)], vl4[dt>>1][2*(dt&1)+1]);
            #pragma unroll
            for (int dt = 0; dt < 8; dt++)
                mma_fp16(o[dt], pal, vh4[dt>>1][2*(dt&1)], vh4[dt>>1][2*(dt&1)+1]);
        }
        __syncthreads();
    }

    // ---- finalize ----
    l0 += __shfl_xor_sync(0xffffffffu, l0, 1);
    l0 += __shfl_xor_sync(0xffffffffu, l0, 2);
    l1 += __shfl_xor_sync(0xffffffffu, l1, 1);
    l1 += __shfl_xor_sync(0xffffffffu, l1, 2);
    const float inv0 = 1.f / l0;
    const float inv1 = 1.f / l1;

    float* out0 = out + ((size_t)(b*T_ + rg0))*C_ + h*D_;
    float* out1 = out + ((size_t)(b*T_ + rg1))*C_ + h*D_;
    #pragma unroll
    for (int dt = 0; dt < 8; dt++) {
        *(float2*)(out0 + dt*8 + 2*lc) = make_float2(o[dt][0]*inv0, o[dt][1]*inv0);
        *(float2*)(out1 + dt*8 + 2*lc) = make_float2(o[dt][2]*inv1, o[dt][3]*inv1);
    }
}

// ----------------------------------------------------------------------------
extern "C" void kernel_launch(void* const* d_in, const int* in_sizes, int n_in,
                              void* d_out, int out_size)
{
    const float* x_norm = (const float*)d_in[0];
    const float* xt_cur = (const float*)d_in[1];
    const float* W_attn = (const float*)d_in[2];
    const float* b_attn = (const float*)d_in[3];
    float* out = (float*)d_out;

    cudaFuncSetAttribute(gemm_qk_kernel,
                         cudaFuncAttributeMaxDynamicSharedMemorySize, GEMM_SMEM_BYTES);
    cudaFuncSetAttribute(attn_kernel,
                         cudaFuncAttributeMaxDynamicSharedMemorySize, ATTN_SMEM_BYTES);

    prep_x_kernel<<<(M_GEMM*K_GEMM/2)/256, 256>>>(x_norm);
    prep_w_kernel<<<dim3(N_GEMM/32, K_GEMM/32), dim3(32, 8)>>>(W_attn);
    prep_v_kernel<<<dim3(T_/32, D_/32, BH_), dim3(32, 8)>>>(xt_cur);

    dim3 g1(N_GEMM/128, M_GEMM/128);   // (16, 32)
    gemm_qk_kernel<<<g1, 256, GEMM_SMEM_BYTES>>>(b_attn);

    dim3 g2(T_/128, B_*H_);            // (16, 32)
    attn_kernel<<<g2, 256, ATTN_SMEM_BYTES>>>(out);
}